// round 1
// baseline (speedup 1.0000x reference)
#include <cuda_runtime.h>
#include <math_constants.h>

#define BATCH 2
#define C 256
#define N 4096
#define KCH 16     // k-chunk
#define TM 64      // tile rows (m)
#define TN 128     // tile cols (n)

// ---------------- device scratch (allocation-free rule: static globals) ----------------
__device__ float g_Wt[2][C * C];              // transposed weights  [dir][c'][c]
__device__ float g_M[2][BATCH][C * N];        // row projections     [dir][b][c][pos]   (16 MB)
__device__ float g_S[2][BATCH][N * N];        // raw logits scratch  [dir][b][row][col] (268 MB)
__device__ float g_u[2][BATCH][N];            // gate-projected row features, indexed by col
__device__ float g_rm[2][BATCH][N];           // row max
__device__ float g_rs[2][BATCH][N];           // row sum-exp

// ---------------- K0: transpose weights ----------------
__global__ void k_transpose(const float* __restrict__ Wex, const float* __restrict__ Wq) {
    int d = blockIdx.y;
    const float* W = d ? Wq : Wex;
    int idx = blockIdx.x * 256 + threadIdx.x;   // idx = c*256 + c'
    int c = idx >> 8, cp = idx & 255;
    g_Wt[d][cp * C + c] = W[idx];
}

// ---------------- Ku: u[d][b][j] = sum_c g[c] * Xrow[b][c][j] ----------------
__global__ void k_u(const float* __restrict__ ex, const float* __restrict__ qf,
                    const float* __restrict__ gate) {
    __shared__ float gs[C];
    int d = blockIdx.z, b = blockIdx.y;
    gs[threadIdx.x] = gate[threadIdx.x];
    __syncthreads();
    const float* X = (d == 0 ? ex : qf) + (size_t)b * C * N;
    int j = blockIdx.x * 256 + threadIdx.x;
    float acc = 0.f;
#pragma unroll 8
    for (int c = 0; c < C; c++) acc += gs[c] * X[(size_t)c * N + j];
    g_u[d][b][j] = acc;
}

// ---------------- shared 64x128 fp32 GEMM tile body (K=256) ----------------
// A: [k][m] row-major with leading dim lda; B: [k][n] leading dim ldb.
__device__ __forceinline__ void gemm64x128(
    const float* __restrict__ A, int lda,
    const float* __restrict__ B, int ldb,
    int m0, int n0,
    float As[2][KCH][TM], float Bs[2][KCH][TN],
    float acc[4][8])
{
    const int t  = threadIdx.x;
    const int ka = t >> 4;
    const int ma = (t & 15) * 4;
    const int nb = (t & 15) * 8;
    const int ty4 = (t >> 4) * 4;
    const int tx8 = (t & 15) * 8;

#pragma unroll
    for (int i = 0; i < 4; i++)
#pragma unroll
        for (int j = 0; j < 8; j++) acc[i][j] = 0.f;

    // prologue: chunk kc=0
    float4 av  = *(const float4*)(A + (size_t)ka * lda + m0 + ma);
    float4 bv0 = *(const float4*)(B + (size_t)ka * ldb + n0 + nb);
    float4 bv1 = *(const float4*)(B + (size_t)ka * ldb + n0 + nb + 4);
    *(float4*)&As[0][ka][ma]     = av;
    *(float4*)&Bs[0][ka][nb]     = bv0;
    *(float4*)&Bs[0][ka][nb + 4] = bv1;
    __syncthreads();

    int buf = 0;
    for (int kc = 0; kc < C; kc += KCH) {
        bool more = (kc + KCH) < C;
        if (more) {
            av  = *(const float4*)(A + (size_t)(kc + KCH + ka) * lda + m0 + ma);
            bv0 = *(const float4*)(B + (size_t)(kc + KCH + ka) * ldb + n0 + nb);
            bv1 = *(const float4*)(B + (size_t)(kc + KCH + ka) * ldb + n0 + nb + 4);
        }
#pragma unroll
        for (int k = 0; k < KCH; k++) {
            float a_[4], b_[8];
            *(float4*)a_       = *(const float4*)&As[buf][k][ty4];
            *(float4*)(b_)     = *(const float4*)&Bs[buf][k][tx8];
            *(float4*)(b_ + 4) = *(const float4*)&Bs[buf][k][tx8 + 4];
#pragma unroll
            for (int i = 0; i < 4; i++)
#pragma unroll
                for (int j = 0; j < 8; j++)
                    acc[i][j] += a_[i] * b_[j];
        }
        if (more) {
            *(float4*)&As[buf ^ 1][ka][ma]     = av;
            *(float4*)&Bs[buf ^ 1][ka][nb]     = bv0;
            *(float4*)&Bs[buf ^ 1][ka][nb + 4] = bv1;
        }
        __syncthreads();
        buf ^= 1;
    }
}

// ---------------- K1: M[d][b] = Wt[d]^T-style GEMM: [c][pos] ----------------
__global__ void __launch_bounds__(256) k_mproj(const float* __restrict__ ex,
                                               const float* __restrict__ qf) {
    __shared__ float As[2][KCH][TM];
    __shared__ float Bs[2][KCH][TN];
    int z = blockIdx.z, d = z >> 1, b = z & 1;
    const float* A  = g_Wt[d];                               // [c'][c], lda=C
    const float* Bm = (d == 0 ? ex : qf) + (size_t)b * C * N; // [c'][pos], ldb=N
    float* Out = g_M[d][b];
    int m0 = blockIdx.y * TM;
    int n0 = blockIdx.x * TN;
    float acc[4][8];
    gemm64x128(A, C, Bm, N, m0, n0, As, Bs, acc);
    int t = threadIdx.x, ty4 = (t >> 4) * 4, tx8 = (t & 15) * 8;
#pragma unroll
    for (int i = 0; i < 4; i++) {
        float4 o0 = make_float4(acc[i][0], acc[i][1], acc[i][2], acc[i][3]);
        float4 o1 = make_float4(acc[i][4], acc[i][5], acc[i][6], acc[i][7]);
        *(float4*)(Out + (size_t)(m0 + ty4 + i) * N + n0 + tx8)     = o0;
        *(float4*)(Out + (size_t)(m0 + ty4 + i) * N + n0 + tx8 + 4) = o1;
    }
}

// ---------------- K2: logits GEMM + online softmax stats + mask ----------------
__global__ void __launch_bounds__(256) k_attn(const float* __restrict__ ex,
                                              const float* __restrict__ qf,
                                              float* __restrict__ out) {
    __shared__ float As[2][KCH][TM];
    __shared__ float Bs[2][KCH][TN];
    int d = blockIdx.z, b = blockIdx.y;
    const float* A  = g_M[d][b];                               // [c][row-pos], lda=N
    const float* Bm = (d == 0 ? qf : ex) + (size_t)b * C * N;  // [c][col-pos], ldb=N
    const float* u  = g_u[d][b];
    float* S = g_S[d][b];
    int e0 = blockIdx.x * TM;
    int t = threadIdx.x, ty4 = (t >> 4) * 4, tx8 = (t & 15) * 8;

    float m_run[4], s_run[4], t_run[4];
#pragma unroll
    for (int i = 0; i < 4; i++) { m_run[i] = -CUDART_INF_F; s_run[i] = 0.f; t_run[i] = 0.f; }

    for (int q0 = 0; q0 < N; q0 += TN) {
        float acc[4][8];
        gemm64x128(A, N, Bm, N, e0, q0, As, Bs, acc);

        float uv[8];
        *(float4*)uv       = *(const float4*)(u + q0 + tx8);
        *(float4*)(uv + 4) = *(const float4*)(u + q0 + tx8 + 4);

#pragma unroll
        for (int i = 0; i < 4; i++) {
            float mx = acc[i][0];
#pragma unroll
            for (int j = 1; j < 8; j++) mx = fmaxf(mx, acc[i][j]);
#pragma unroll
            for (int off = 8; off > 0; off >>= 1)
                mx = fmaxf(mx, __shfl_xor_sync(0xffffffffu, mx, off));
            float mn = fmaxf(m_run[i], mx);
            float sc = __expf(m_run[i] - mn);   // first tile: exp(-inf)=0, s=t=0 -> ok
            float ps = 0.f, pu = 0.f;
#pragma unroll
            for (int j = 0; j < 8; j++) {
                float p = __expf(acc[i][j] - mn);
                ps += p; pu += p * uv[j];
            }
#pragma unroll
            for (int off = 8; off > 0; off >>= 1) {
                ps += __shfl_xor_sync(0xffffffffu, ps, off);
                pu += __shfl_xor_sync(0xffffffffu, pu, off);
            }
            s_run[i] = s_run[i] * sc + ps;
            t_run[i] = t_run[i] * sc + pu;
            m_run[i] = mn;
            // spill raw logits (row-major, coalesced)
            *(float4*)(S + (size_t)(e0 + ty4 + i) * N + q0 + tx8) =
                make_float4(acc[i][0], acc[i][1], acc[i][2], acc[i][3]);
            *(float4*)(S + (size_t)(e0 + ty4 + i) * N + q0 + tx8 + 4) =
                make_float4(acc[i][4], acc[i][5], acc[i][6], acc[i][7]);
        }
    }

    if ((t & 15) == 0) {
#pragma unroll
        for (int i = 0; i < 4; i++) {
            int e = e0 + ty4 + i;
            g_rm[d][b][e] = m_run[i];
            g_rs[d][b][e] = s_run[i];
            float zv = t_run[i] / s_run[i];
            float mk = 1.f / (1.f + __expf(-zv));
            // d=0 -> ex_mask [0,8192); d=1 -> q_mask [8192,16384)
            out[(size_t)d * (BATCH * N) + (size_t)b * N + e] = mk;
        }
    }
}

// ---------------- K3: normalize + transpose-write A ----------------
__global__ void __launch_bounds__(256) k_norm_t(float* __restrict__ out) {
    __shared__ float T[64][65];
    int z = blockIdx.z, d = z >> 1, b = z & 1;
    const float* S  = g_S[d][b];
    const float* rm = g_rm[d][b];
    const float* rs = g_rs[d][b];
    float* Aout = out + 16384 + (size_t)d * (size_t)BATCH * N * N + (size_t)b * (size_t)N * N;
    int e0 = blockIdx.y * 64, q0 = blockIdx.x * 64;
    int t = threadIdx.x;

#pragma unroll
    for (int it = 0; it < 4; it++) {
        int e  = (t >> 4) + it * 16;
        int q4 = (t & 15) * 4;
        float4 v = *(const float4*)(S + (size_t)(e0 + e) * N + q0 + q4);
        float m    = rm[e0 + e];
        float rinv = __frcp_rn(rs[e0 + e]);
        T[e][q4 + 0] = __expf(v.x - m) * rinv;
        T[e][q4 + 1] = __expf(v.y - m) * rinv;
        T[e][q4 + 2] = __expf(v.z - m) * rinv;
        T[e][q4 + 3] = __expf(v.w - m) * rinv;
    }
    __syncthreads();
#pragma unroll
    for (int it = 0; it < 4; it++) {
        int q  = (t >> 4) + it * 16;
        int e4 = (t & 15) * 4;
        float4 o;
        o.x = T[e4 + 0][q];
        o.y = T[e4 + 1][q];
        o.z = T[e4 + 2][q];
        o.w = T[e4 + 3][q];
        *(float4*)(Aout + (size_t)(q0 + q) * N + e0 + e4) = o;
    }
}

// ---------------- launch ----------------
extern "C" void kernel_launch(void* const* d_in, const int* in_sizes, int n_in,
                              void* d_out, int out_size) {
    const float* ex   = (const float*)d_in[0];
    const float* qf   = (const float*)d_in[1];
    const float* Wex  = (const float*)d_in[2];
    const float* Wq   = (const float*)d_in[3];
    const float* gate = (const float*)d_in[4];
    float* out = (float*)d_out;

    k_transpose<<<dim3(256, 2), 256>>>(Wex, Wq);
    k_u        <<<dim3(N / 256, BATCH, 2), 256>>>(ex, qf, gate);
    k_mproj    <<<dim3(N / TN, C / TM, 4), 256>>>(ex, qf);
    k_attn     <<<dim3(N / TM, BATCH, 2), 256>>>(ex, qf, out);
    k_norm_t   <<<dim3(N / 64, N / 64, 4), 256>>>(out);
}

// round 2
// speedup vs baseline: 1.3359x; 1.3359x over previous
#include <cuda_runtime.h>
#include <math_constants.h>

#define BATCH 2
#define C 256
#define N 4096
#define KCH 16     // k-chunk
#define TM 64      // tile rows (m)
#define TN 128     // tile cols (n)

typedef unsigned long long ull_t;

// ---------------- device scratch (allocation-free rule: static globals) ----------------
__device__ float g_Wt[2][C * C];              // transposed weights  [dir][c'][c]
__device__ float g_M[2][BATCH][C * N];        // row projections     [dir][b][c][pos]
__device__ float g_S[2][BATCH][N * N];        // raw logits scratch  [dir][b][row][col]
__device__ float g_u[2][BATCH][N];            // gate-projected row features
__device__ float g_rm[2][BATCH][N];           // row max
__device__ float g_rs[2][BATCH][N];           // row sum-exp

union F4U { float4 f; ull_t u[2]; float s[4]; };

__device__ __forceinline__ void fma2(ull_t& d, ull_t a, ull_t b) {
    asm("fma.rn.f32x2 %0, %1, %2, %0;" : "+l"(d) : "l"(a), "l"(b));
}
__device__ __forceinline__ float lo2(ull_t x) { return __uint_as_float((unsigned)x); }
__device__ __forceinline__ float hi2(ull_t x) { return __uint_as_float((unsigned)(x >> 32)); }

// ---------------- K0: transpose weights ----------------
__global__ void k_transpose(const float* __restrict__ Wex, const float* __restrict__ Wq) {
    int d = blockIdx.y;
    const float* W = d ? Wq : Wex;
    int idx = blockIdx.x * 256 + threadIdx.x;
    int c = idx >> 8, cp = idx & 255;
    g_Wt[d][cp * C + c] = W[idx];
}

// ---------------- Ku: u[d][b][j] = sum_c g[c] * Xrow[b][c][j] ----------------
__global__ void k_u(const float* __restrict__ ex, const float* __restrict__ qf,
                    const float* __restrict__ gate) {
    __shared__ float gs[C];
    int d = blockIdx.z, b = blockIdx.y;
    gs[threadIdx.x] = gate[threadIdx.x];
    __syncthreads();
    const float* X = (d == 0 ? ex : qf) + (size_t)b * C * N;
    int j = blockIdx.x * 256 + threadIdx.x;
    float acc = 0.f;
#pragma unroll 8
    for (int c = 0; c < C; c++) acc += gs[c] * X[(size_t)c * N + j];
    g_u[d][b][j] = acc;
}

// ---------------- 64x128 fp32x2 GEMM tile body (K=256) ----------------
// A: [k][m] leading dim lda; B: [k][n] leading dim ldb. 256 threads.
// Thread (ty=t>>4, tx=t&15): rows m0+ty*4..+3, cols {n0+tx*4..+3, n0+64+tx*4..+3}.
// accp[i][0..3] = packed col-pairs {tx*4+0/1, tx*4+2/3, 64+tx*4+0/1, 64+tx*4+2/3}.
__device__ __forceinline__ void gemm_f32x2(
    const float* __restrict__ A, int lda,
    const float* __restrict__ B, int ldb,
    int m0, int n0,
    float As2[2][KCH][TM * 2], float Bs[2][KCH][TN],
    ull_t accp[4][4])
{
    const int t   = threadIdx.x;
    const int ka  = t >> 4;           // A loader row 0..15
    const int ca4 = (t & 15) * 4;     // A loader col
    const int kb  = t >> 5;           // B loader row 0..7 (and +8)
    const int cb4 = (t & 31) * 4;     // B loader col
    const int ty  = t >> 4;
    const int tx  = t & 15;

#pragma unroll
    for (int i = 0; i < 4; i++)
#pragma unroll
        for (int j = 0; j < 4; j++) accp[i][j] = 0ull;

    // prologue: chunk 0
    float4 av  = *(const float4*)(A + (size_t)ka * lda + m0 + ca4);
    float4 bv0 = *(const float4*)(B + (size_t)kb * ldb + n0 + cb4);
    float4 bv1 = *(const float4*)(B + (size_t)(kb + 8) * ldb + n0 + cb4);
    {
        F4U d0, d1;
        d0.s[0] = av.x; d0.s[1] = av.x; d0.s[2] = av.y; d0.s[3] = av.y;
        d1.s[0] = av.z; d1.s[1] = av.z; d1.s[2] = av.w; d1.s[3] = av.w;
        *(float4*)&As2[0][ka][ca4 * 2]     = d0.f;
        *(float4*)&As2[0][ka][ca4 * 2 + 4] = d1.f;
        *(float4*)&Bs[0][kb][cb4]     = bv0;
        *(float4*)&Bs[0][kb + 8][cb4] = bv1;
    }
    __syncthreads();

    int buf = 0;
    for (int kc = 0; kc < C; kc += KCH) {
        bool more = (kc + KCH) < C;
        if (more) {
            av  = *(const float4*)(A + (size_t)(kc + KCH + ka) * lda + m0 + ca4);
            bv0 = *(const float4*)(B + (size_t)(kc + KCH + kb) * ldb + n0 + cb4);
            bv1 = *(const float4*)(B + (size_t)(kc + KCH + kb + 8) * ldb + n0 + cb4);
        }
#pragma unroll
        for (int k = 0; k < KCH; k++) {
            F4U af0, af1, bf0, bf1;
            af0.f = *(const float4*)&As2[buf][k][ty * 8];
            af1.f = *(const float4*)&As2[buf][k][ty * 8 + 4];
            bf0.f = *(const float4*)&Bs[buf][k][tx * 4];
            bf1.f = *(const float4*)&Bs[buf][k][64 + tx * 4];
            ull_t ar0 = af0.u[0], ar1 = af0.u[1], ar2 = af1.u[0], ar3 = af1.u[1];
            ull_t bp0 = bf0.u[0], bp1 = bf0.u[1], bp2 = bf1.u[0], bp3 = bf1.u[1];
            fma2(accp[0][0], ar0, bp0); fma2(accp[0][1], ar0, bp1);
            fma2(accp[0][2], ar0, bp2); fma2(accp[0][3], ar0, bp3);
            fma2(accp[1][0], ar1, bp0); fma2(accp[1][1], ar1, bp1);
            fma2(accp[1][2], ar1, bp2); fma2(accp[1][3], ar1, bp3);
            fma2(accp[2][0], ar2, bp0); fma2(accp[2][1], ar2, bp1);
            fma2(accp[2][2], ar2, bp2); fma2(accp[2][3], ar2, bp3);
            fma2(accp[3][0], ar3, bp0); fma2(accp[3][1], ar3, bp1);
            fma2(accp[3][2], ar3, bp2); fma2(accp[3][3], ar3, bp3);
        }
        if (more) {
            F4U d0, d1;
            d0.s[0] = av.x; d0.s[1] = av.x; d0.s[2] = av.y; d0.s[3] = av.y;
            d1.s[0] = av.z; d1.s[1] = av.z; d1.s[2] = av.w; d1.s[3] = av.w;
            *(float4*)&As2[buf ^ 1][ka][ca4 * 2]     = d0.f;
            *(float4*)&As2[buf ^ 1][ka][ca4 * 2 + 4] = d1.f;
            *(float4*)&Bs[buf ^ 1][kb][cb4]     = bv0;
            *(float4*)&Bs[buf ^ 1][kb + 8][cb4] = bv1;
        }
        __syncthreads();
        buf ^= 1;
    }
}

// ---------------- K1: M projection GEMM ----------------
__global__ void __launch_bounds__(256) k_mproj(const float* __restrict__ ex,
                                               const float* __restrict__ qf) {
    __shared__ float As2[2][KCH][TM * 2];
    __shared__ float Bs[2][KCH][TN];
    int z = blockIdx.z, d = z >> 1, b = z & 1;
    const float* A  = g_Wt[d];                                 // [c'][c] as (k,m)
    const float* Bm = (d == 0 ? ex : qf) + (size_t)b * C * N;  // [c][pos]
    float* Out = g_M[d][b];
    int m0 = blockIdx.y * TM;
    int n0 = blockIdx.x * TN;
    ull_t accp[4][4];
    gemm_f32x2(A, C, Bm, N, m0, n0, As2, Bs, accp);
    int t = threadIdx.x, ty = t >> 4, tx = t & 15;
#pragma unroll
    for (int i = 0; i < 4; i++) {
        float4 o0 = make_float4(lo2(accp[i][0]), hi2(accp[i][0]),
                                lo2(accp[i][1]), hi2(accp[i][1]));
        float4 o1 = make_float4(lo2(accp[i][2]), hi2(accp[i][2]),
                                lo2(accp[i][3]), hi2(accp[i][3]));
        *(float4*)(Out + (size_t)(m0 + ty * 4 + i) * N + n0 + tx * 4)      = o0;
        *(float4*)(Out + (size_t)(m0 + ty * 4 + i) * N + n0 + 64 + tx * 4) = o1;
    }
}

// ---------------- K2: logits GEMM + online softmax stats + mask ----------------
__global__ void __launch_bounds__(256) k_attn(const float* __restrict__ ex,
                                              const float* __restrict__ qf,
                                              float* __restrict__ out) {
    __shared__ float As2[2][KCH][TM * 2];
    __shared__ float Bs[2][KCH][TN];
    int d = blockIdx.z, b = blockIdx.y;
    const float* A  = g_M[d][b];                               // [c][row-pos]
    const float* Bm = (d == 0 ? qf : ex) + (size_t)b * C * N;  // [c][col-pos]
    const float* u  = g_u[d][b];
    float* S = g_S[d][b];
    int e0 = blockIdx.x * TM;
    int t = threadIdx.x, ty = t >> 4, tx = t & 15;

    float m_run[4], s_run[4], t_run[4];
#pragma unroll
    for (int i = 0; i < 4; i++) { m_run[i] = -CUDART_INF_F; s_run[i] = 0.f; t_run[i] = 0.f; }

    for (int q0 = 0; q0 < N; q0 += TN) {
        ull_t accp[4][4];
        gemm_f32x2(A, N, Bm, N, e0, q0, As2, Bs, accp);

        float4 uv0 = *(const float4*)(u + q0 + tx * 4);
        float4 uv1 = *(const float4*)(u + q0 + 64 + tx * 4);

#pragma unroll
        for (int i = 0; i < 4; i++) {
            float v[8];
            v[0] = lo2(accp[i][0]); v[1] = hi2(accp[i][0]);
            v[2] = lo2(accp[i][1]); v[3] = hi2(accp[i][1]);
            v[4] = lo2(accp[i][2]); v[5] = hi2(accp[i][2]);
            v[6] = lo2(accp[i][3]); v[7] = hi2(accp[i][3]);

            float mx = v[0];
#pragma unroll
            for (int j = 1; j < 8; j++) mx = fmaxf(mx, v[j]);
#pragma unroll
            for (int off = 8; off > 0; off >>= 1)
                mx = fmaxf(mx, __shfl_xor_sync(0xffffffffu, mx, off));
            float mn = fmaxf(m_run[i], mx);
            float sc = __expf(m_run[i] - mn);
            float ps = 0.f, pu = 0.f;
            float uw[8] = {uv0.x, uv0.y, uv0.z, uv0.w, uv1.x, uv1.y, uv1.z, uv1.w};
#pragma unroll
            for (int j = 0; j < 8; j++) {
                float p = __expf(v[j] - mn);
                ps += p; pu += p * uw[j];
            }
#pragma unroll
            for (int off = 8; off > 0; off >>= 1) {
                ps += __shfl_xor_sync(0xffffffffu, ps, off);
                pu += __shfl_xor_sync(0xffffffffu, pu, off);
            }
            s_run[i] = s_run[i] * sc + ps;
            t_run[i] = t_run[i] * sc + pu;
            m_run[i] = mn;

            int e = e0 + ty * 4 + i;
            *(float4*)(S + (size_t)e * N + q0 + tx * 4) =
                make_float4(v[0], v[1], v[2], v[3]);
            *(float4*)(S + (size_t)e * N + q0 + 64 + tx * 4) =
                make_float4(v[4], v[5], v[6], v[7]);
        }
    }

    if (tx == 0) {
#pragma unroll
        for (int i = 0; i < 4; i++) {
            int e = e0 + ty * 4 + i;
            g_rm[d][b][e] = m_run[i];
            g_rs[d][b][e] = s_run[i];
            float zv = t_run[i] / s_run[i];
            float mk = 1.f / (1.f + __expf(-zv));
            out[(size_t)d * (BATCH * N) + (size_t)b * N + e] = mk;
        }
    }
}

// ---------------- K3: normalize + transpose-write A ----------------
__global__ void __launch_bounds__(256) k_norm_t(float* __restrict__ out) {
    __shared__ float T[64][65];
    int z = blockIdx.z, d = z >> 1, b = z & 1;
    const float* S  = g_S[d][b];
    const float* rm = g_rm[d][b];
    const float* rs = g_rs[d][b];
    float* Aout = out + 16384 + (size_t)d * (size_t)BATCH * N * N + (size_t)b * (size_t)N * N;
    int e0 = blockIdx.y * 64, q0 = blockIdx.x * 64;
    int t = threadIdx.x;

#pragma unroll
    for (int it = 0; it < 4; it++) {
        int e  = (t >> 4) + it * 16;
        int q4 = (t & 15) * 4;
        float4 v = *(const float4*)(S + (size_t)(e0 + e) * N + q0 + q4);
        float m    = rm[e0 + e];
        float rinv = __frcp_rn(rs[e0 + e]);
        T[e][q4 + 0] = __expf(v.x - m) * rinv;
        T[e][q4 + 1] = __expf(v.y - m) * rinv;
        T[e][q4 + 2] = __expf(v.z - m) * rinv;
        T[e][q4 + 3] = __expf(v.w - m) * rinv;
    }
    __syncthreads();
#pragma unroll
    for (int it = 0; it < 4; it++) {
        int q  = (t >> 4) + it * 16;
        int e4 = (t & 15) * 4;
        float4 o;
        o.x = T[e4 + 0][q];
        o.y = T[e4 + 1][q];
        o.z = T[e4 + 2][q];
        o.w = T[e4 + 3][q];
        *(float4*)(Aout + (size_t)(q0 + q) * N + e0 + e4) = o;
    }
}

// ---------------- launch ----------------
extern "C" void kernel_launch(void* const* d_in, const int* in_sizes, int n_in,
                              void* d_out, int out_size) {
    const float* ex   = (const float*)d_in[0];
    const float* qf   = (const float*)d_in[1];
    const float* Wex  = (const float*)d_in[2];
    const float* Wq   = (const float*)d_in[3];
    const float* gate = (const float*)d_in[4];
    float* out = (float*)d_out;

    k_transpose<<<dim3(256, 2), 256>>>(Wex, Wq);
    k_u        <<<dim3(N / 256, BATCH, 2), 256>>>(ex, qf, gate);
    k_mproj    <<<dim3(N / TN, C / TM, 4), 256>>>(ex, qf);
    k_attn     <<<dim3(N / TM, BATCH, 2), 256>>>(ex, qf, out);
    k_norm_t   <<<dim3(N / 64, N / 64, 4), 256>>>(out);
}

// round 4
// speedup vs baseline: 3.0654x; 2.2947x over previous
#include <cuda_runtime.h>
#include <cuda_bf16.h>
#include <math_constants.h>
#include <cstdint>

#define BATCH 2
#define C 256
#define N 4096
#define KCH 16
#define TM 64
#define TN 128

typedef unsigned long long ull_t;

// ---------------- device scratch ----------------
__device__ float g_Wt[2][C * C];
__device__ float g_S[2][BATCH][N * N];          // raw logits spill
__device__ float g_u[2][BATCH][N];
__device__ float g_rm[2][BATCH][N];
__device__ float g_rs[2][BATCH][N];
// mma-fragment-ordered operands (uint = bf16x2 pair along k)
// A: per (d,b): [mtile(256)][kstep(16)][lane(32)][r(4)]  -> 524288 words
__device__ uint32_t g_Afh[2 * BATCH * 524288];
__device__ uint32_t g_Afl[2 * BATCH * 524288];
// B: per (src,b): [ntile(512)][kstep(16)][lane(32)][r(2)] -> 524288 words
__device__ uint32_t g_Bfh[2 * BATCH * 524288];
__device__ uint32_t g_Bfl[2 * BATCH * 524288];

union F4U { float4 f; ull_t u[2]; float s[4]; };

__device__ __forceinline__ void fma2(ull_t& d, ull_t a, ull_t b) {
    asm("fma.rn.f32x2 %0, %1, %2, %0;" : "+l"(d) : "l"(a), "l"(b));
}
__device__ __forceinline__ float lo2(ull_t x) { return __uint_as_float((unsigned)x); }
__device__ __forceinline__ float hi2(ull_t x) { return __uint_as_float((unsigned)(x >> 32)); }

__device__ __forceinline__ void bf16split(float v, unsigned short& h, unsigned short& l) {
    __nv_bfloat16 hb = __float2bfloat16_rn(v);
    float lr = v - __bfloat162float(hb);
    h = __bfloat16_as_ushort(hb);
    l = __bfloat16_as_ushort(__float2bfloat16_rn(lr));
}

// fragment word offsets (within one (d,b) / (src,b) plane)
__device__ __forceinline__ uint32_t awoff(int m, int k) {
    uint32_t mtile = m >> 4, kstep = k >> 4;
    uint32_t lane = ((m & 7) << 2) | ((k & 7) >> 1);
    uint32_t r = ((m >> 3) & 1) | (((k >> 3) & 1) << 1);
    return ((mtile * 16 + kstep) << 7) + (lane << 2) + r;
}
__device__ __forceinline__ uint32_t bwoff(int n, int k) {
    uint32_t ntile = n >> 3, kstep = k >> 4;
    uint32_t lane = ((n & 7) << 2) | ((k & 7) >> 1);
    uint32_t r = (k >> 3) & 1;
    return ((ntile * 16 + kstep) << 6) + (lane << 1) + r;
}

__device__ __forceinline__ void mma_bf16(float* c, const uint32_t* a, const uint32_t* b) {
    asm volatile(
        "mma.sync.aligned.m16n8k16.row.col.f32.bf16.bf16.f32 "
        "{%0,%1,%2,%3}, {%4,%5,%6,%7}, {%8,%9}, {%0,%1,%2,%3};"
        : "+f"(c[0]), "+f"(c[1]), "+f"(c[2]), "+f"(c[3])
        : "r"(a[0]), "r"(a[1]), "r"(a[2]), "r"(a[3]), "r"(b[0]), "r"(b[1]));
}

// ---------------- K0: transpose weights ----------------
__global__ void k_transpose(const float* __restrict__ Wex, const float* __restrict__ Wq) {
    int d = blockIdx.y;
    const float* W = d ? Wq : Wex;
    int idx = blockIdx.x * 256 + threadIdx.x;
    int c = idx >> 8, cp = idx & 255;
    g_Wt[d][cp * C + c] = W[idx];
}

// ---------------- Ku ----------------
__global__ void k_u(const float* __restrict__ ex, const float* __restrict__ qf,
                    const float* __restrict__ gate) {
    __shared__ float gs[C];
    int d = blockIdx.z, b = blockIdx.y;
    gs[threadIdx.x] = gate[threadIdx.x];
    __syncthreads();
    const float* X = (d == 0 ? ex : qf) + (size_t)b * C * N;
    int j = blockIdx.x * 256 + threadIdx.x;
    float acc = 0.f;
#pragma unroll 8
    for (int c = 0; c < C; c++) acc += gs[c] * X[(size_t)c * N + j];
    g_u[d][b][j] = acc;
}

// ---------------- k_bfrag: X[c][n] -> B fragments (hi/lo) ----------------
__global__ void __launch_bounds__(256) k_bfrag(const float* __restrict__ ex,
                                               const float* __restrict__ qf) {
    __shared__ float T[64][65];
    int z = blockIdx.z, src = z >> 1, b = z & 1;
    const float* X = (src == 0 ? ex : qf) + (size_t)b * C * N;
    int c0 = blockIdx.y * 64, n0 = blockIdx.x * 64;
    int t = threadIdx.x;
#pragma unroll
    for (int it = 0; it < 4; it++) {
        int c = (t >> 4) + it * 16;
        int n4 = (t & 15) * 4;
        float4 v = *(const float4*)(X + (size_t)(c0 + c) * N + n0 + n4);
        T[c][n4 + 0] = v.x; T[c][n4 + 1] = v.y; T[c][n4 + 2] = v.z; T[c][n4 + 3] = v.w;
    }
    __syncthreads();
    uint32_t bb = (uint32_t)(src * BATCH + b) * 524288u;
#pragma unroll
    for (int it = 0; it < 4; it++) {
        int nl = (t >> 4) + it * 16;
        int c4 = (t & 15) * 4;
        int n = n0 + nl;
        unsigned short h[4], l[4];
#pragma unroll
        for (int k = 0; k < 4; k++) bf16split(T[c4 + k][nl], h[k], l[k]);
        int cg = c0 + c4;
        uint32_t w0 = bwoff(n, cg), w1 = bwoff(n, cg + 2);
        g_Bfh[bb + w0] = (uint32_t)h[0] | ((uint32_t)h[1] << 16);
        g_Bfh[bb + w1] = (uint32_t)h[2] | ((uint32_t)h[3] << 16);
        g_Bfl[bb + w0] = (uint32_t)l[0] | ((uint32_t)l[1] << 16);
        g_Bfl[bb + w1] = (uint32_t)l[2] | ((uint32_t)l[3] << 16);
    }
}

// ---------------- K1: M projection GEMM (f32x2) -> A fragments ----------------
__global__ void __launch_bounds__(256) k_mproj(const float* __restrict__ ex,
                                               const float* __restrict__ qf) {
    __shared__ float As2[2][KCH][TM * 2];
    __shared__ float Bs[2][KCH][TN];
    int z = blockIdx.z, d = z >> 1, b = z & 1;
    const float* A  = g_Wt[d];
    const float* Bm = (d == 0 ? ex : qf) + (size_t)b * C * N;
    int m0 = blockIdx.y * TM;
    int n0 = blockIdx.x * TN;

    const int t = threadIdx.x;
    const int ka = t >> 4, ca4 = (t & 15) * 4;
    const int kb = t >> 5, cb4 = (t & 31) * 4;
    const int ty = t >> 4, tx = t & 15;

    ull_t accp[4][4];
#pragma unroll
    for (int i = 0; i < 4; i++)
#pragma unroll
        for (int j = 0; j < 4; j++) accp[i][j] = 0ull;

    float4 av  = *(const float4*)(A + (size_t)ka * C + m0 + ca4);
    float4 bv0 = *(const float4*)(Bm + (size_t)kb * N + n0 + cb4);
    float4 bv1 = *(const float4*)(Bm + (size_t)(kb + 8) * N + n0 + cb4);
    {
        F4U d0, d1;
        d0.s[0] = av.x; d0.s[1] = av.x; d0.s[2] = av.y; d0.s[3] = av.y;
        d1.s[0] = av.z; d1.s[1] = av.z; d1.s[2] = av.w; d1.s[3] = av.w;
        *(float4*)&As2[0][ka][ca4 * 2]     = d0.f;
        *(float4*)&As2[0][ka][ca4 * 2 + 4] = d1.f;
        *(float4*)&Bs[0][kb][cb4]     = bv0;
        *(float4*)&Bs[0][kb + 8][cb4] = bv1;
    }
    __syncthreads();

    int buf = 0;
    for (int kc = 0; kc < C; kc += KCH) {
        bool more = (kc + KCH) < C;
        if (more) {
            av  = *(const float4*)(A + (size_t)(kc + KCH + ka) * C + m0 + ca4);
            bv0 = *(const float4*)(Bm + (size_t)(kc + KCH + kb) * N + n0 + cb4);
            bv1 = *(const float4*)(Bm + (size_t)(kc + KCH + kb + 8) * N + n0 + cb4);
        }
#pragma unroll
        for (int k = 0; k < KCH; k++) {
            F4U af0, af1, bf0, bf1;
            af0.f = *(const float4*)&As2[buf][k][ty * 8];
            af1.f = *(const float4*)&As2[buf][k][ty * 8 + 4];
            bf0.f = *(const float4*)&Bs[buf][k][tx * 4];
            bf1.f = *(const float4*)&Bs[buf][k][64 + tx * 4];
            ull_t ar0 = af0.u[0], ar1 = af0.u[1], ar2 = af1.u[0], ar3 = af1.u[1];
            ull_t bp0 = bf0.u[0], bp1 = bf0.u[1], bp2 = bf1.u[0], bp3 = bf1.u[1];
            fma2(accp[0][0], ar0, bp0); fma2(accp[0][1], ar0, bp1);
            fma2(accp[0][2], ar0, bp2); fma2(accp[0][3], ar0, bp3);
            fma2(accp[1][0], ar1, bp0); fma2(accp[1][1], ar1, bp1);
            fma2(accp[1][2], ar1, bp2); fma2(accp[1][3], ar1, bp3);
            fma2(accp[2][0], ar2, bp0); fma2(accp[2][1], ar2, bp1);
            fma2(accp[2][2], ar2, bp2); fma2(accp[2][3], ar2, bp3);
            fma2(accp[3][0], ar3, bp0); fma2(accp[3][1], ar3, bp1);
            fma2(accp[3][2], ar3, bp2); fma2(accp[3][3], ar3, bp3);
        }
        if (more) {
            F4U d0, d1;
            d0.s[0] = av.x; d0.s[1] = av.x; d0.s[2] = av.y; d0.s[3] = av.y;
            d1.s[0] = av.z; d1.s[1] = av.z; d1.s[2] = av.w; d1.s[3] = av.w;
            *(float4*)&As2[buf ^ 1][ka][ca4 * 2]     = d0.f;
            *(float4*)&As2[buf ^ 1][ka][ca4 * 2 + 4] = d1.f;
            *(float4*)&Bs[buf ^ 1][kb][cb4]     = bv0;
            *(float4*)&Bs[buf ^ 1][kb + 8][cb4] = bv1;
        }
        __syncthreads();
        buf ^= 1;
    }

    // epilogue: logits-A rows m = pos, k = c'. Write fragment-ordered hi/lo.
    uint32_t ab = (uint32_t)(d * BATCH + b) * 524288u;
    int k0 = m0 + ty * 4;   // even
#pragma unroll
    for (int jj = 0; jj < 8; jj++) {
        int jp = jj >> 1;
        float vv[4];
        if (jj & 1) { vv[0] = hi2(accp[0][jp]); vv[1] = hi2(accp[1][jp]); vv[2] = hi2(accp[2][jp]); vv[3] = hi2(accp[3][jp]); }
        else        { vv[0] = lo2(accp[0][jp]); vv[1] = lo2(accp[1][jp]); vv[2] = lo2(accp[2][jp]); vv[3] = lo2(accp[3][jp]); }
        int pos = n0 + ((jj < 4) ? (tx * 4 + jj) : (64 + tx * 4 + (jj - 4)));
        unsigned short h[4], l[4];
#pragma unroll
        for (int i = 0; i < 4; i++) bf16split(vv[i], h[i], l[i]);
        uint32_t w0 = awoff(pos, k0), w1 = awoff(pos, k0 + 2);
        g_Afh[ab + w0] = (uint32_t)h[0] | ((uint32_t)h[1] << 16);
        g_Afh[ab + w1] = (uint32_t)h[2] | ((uint32_t)h[3] << 16);
        g_Afl[ab + w0] = (uint32_t)l[0] | ((uint32_t)l[1] << 16);
        g_Afl[ab + w1] = (uint32_t)l[2] | ((uint32_t)l[3] << 16);
    }
}

// ---------------- K2: HMMA logits GEMM + online softmax ----------------
// smem: A frags hi(64K)+lo(64K) resident; B hi[2][16K]+lo[2][16K] double-buffered.
#define OFF_AFH 0
#define OFF_AFL 65536
#define OFF_BSH 131072
#define OFF_BSL 163840
#define SMEM_TOT 196608

__global__ void __launch_bounds__(256, 1) k_attn_mma(float* __restrict__ out) {
    extern __shared__ char smc[];
    uint32_t* Afh = (uint32_t*)(smc + OFF_AFH);
    uint32_t* Afl = (uint32_t*)(smc + OFF_AFL);
    uint32_t* Bsh = (uint32_t*)(smc + OFF_BSH);   // [2][4096] words
    uint32_t* Bsl = (uint32_t*)(smc + OFF_BSL);

    int tid = threadIdx.x, w = tid >> 5, lane = tid & 31;
    int panel = blockIdx.x, b = blockIdx.y, d = blockIdx.z;
    int e0 = panel * 128;
    int src = (d == 0) ? 1 : 0;

    const uint32_t* Agh = g_Afh + (size_t)(d * BATCH + b) * 524288 + (size_t)panel * 16384;
    const uint32_t* Agl = g_Afl + (size_t)(d * BATCH + b) * 524288 + (size_t)panel * 16384;
    const uint32_t* Bgh = g_Bfh + (size_t)(src * BATCH + b) * 524288;
    const uint32_t* Bgl = g_Bfl + (size_t)(src * BATCH + b) * 524288;
    const float* uptr = g_u[d][b];
    float* S = g_S[d][b];

    // load A fragments (hi+lo, 64KB each) into smem, coalesced
#pragma unroll
    for (int i = 0; i < 16; i++) {
        int j = tid + i * 256;
        ((uint4*)Afh)[j] = __ldg((const uint4*)Agh + j);
        ((uint4*)Afl)[j] = __ldg((const uint4*)Agl + j);
    }

    // prefetch B chunk 0 (tile 0, kc 0)
    uint4 pfh[4], pfl[4];
#pragma unroll
    for (int i = 0; i < 4; i++) {
        int j = tid + i * 256;                    // 0..1023
        int ntl = j >> 6, w4 = j & 63;
        size_t s4 = (size_t)((0 * 16 + ntl) * 16 + 0) * 16 + w4;
        pfh[i] = __ldg((const uint4*)Bgh + s4);
        pfl[i] = __ldg((const uint4*)Bgl + s4);
    }
#pragma unroll
    for (int i = 0; i < 4; i++) {
        int j = tid + i * 256;
        ((uint4*)Bsh)[j] = pfh[i];
        ((uint4*)Bsl)[j] = pfl[i];
    }
    __syncthreads();

    float m_run[2], s_run[2], t_run[2];
    m_run[0] = m_run[1] = -CUDART_INF_F;
    s_run[0] = s_run[1] = 0.f;
    t_run[0] = t_run[1] = 0.f;

    int buf = 0;
    for (int tile = 0; tile < 32; tile++) {
        float acc[16][4];
#pragma unroll
        for (int nt = 0; nt < 16; nt++)
#pragma unroll
            for (int r = 0; r < 4; r++) acc[nt][r] = 0.f;

        for (int kc = 0; kc < 4; kc++) {
            int gc = tile * 4 + kc;
            bool more = (gc + 1) < 128;
            if (more) {
                int nt2 = (gc + 1) >> 2, kc2 = (gc + 1) & 3;
#pragma unroll
                for (int i = 0; i < 4; i++) {
                    int j = tid + i * 256;
                    int ntl = j >> 6, w4 = j & 63;
                    size_t s4 = (size_t)((nt2 * 16 + ntl) * 16 + kc2 * 4) * 16 + w4;
                    pfh[i] = __ldg((const uint4*)Bgh + s4);
                    pfl[i] = __ldg((const uint4*)Bgl + s4);
                }
            }
            // compute 4 ksteps on current buffer
#pragma unroll
            for (int ks = 0; ks < 4; ks++) {
                int kstep = kc * 4 + ks;
                uint32_t ah[4], al[4];
                *(uint4*)ah = *(const uint4*)(Afh + ((w * 16 + kstep) << 7) + (lane << 2));
                *(uint4*)al = *(const uint4*)(Afl + ((w * 16 + kstep) << 7) + (lane << 2));
#pragma unroll
                for (int h2 = 0; h2 < 2; h2++) {
                    uint32_t bh[8][2], bl[8][2];
#pragma unroll
                    for (int j = 0; j < 8; j++) {
                        int off = (((h2 * 8 + j) * 4 + ks) << 6) + (lane << 1);
                        *(uint2*)bh[j] = *(const uint2*)(Bsh + buf * 4096 + off);
                        *(uint2*)bl[j] = *(const uint2*)(Bsl + buf * 4096 + off);
                    }
#pragma unroll
                    for (int j = 0; j < 8; j++) {
                        int nt = h2 * 8 + j;
                        mma_bf16(acc[nt], ah, bh[j]);
                        mma_bf16(acc[nt], ah, bl[j]);
                        mma_bf16(acc[nt], al, bh[j]);
                    }
                }
            }
            if (more) {
#pragma unroll
                for (int i = 0; i < 4; i++) {
                    int j = tid + i * 256;
                    ((uint4*)Bsh)[(buf ^ 1) * 1024 + j] = pfh[i];
                    ((uint4*)Bsl)[(buf ^ 1) * 1024 + j] = pfl[i];
                }
            }
            __syncthreads();
            buf ^= 1;
        }

        // ---- epilogue: online softmax over this 128-col tile ----
        int q0 = tile * 128;
#pragma unroll
        for (int rr = 0; rr < 2; rr++) {
            int row = e0 + w * 16 + (lane >> 2) + rr * 8;
            // tile max
            float mx = -CUDART_INF_F;
#pragma unroll
            for (int nt = 0; nt < 16; nt++)
                mx = fmaxf(mx, fmaxf(acc[nt][rr * 2], acc[nt][rr * 2 + 1]));
            mx = fmaxf(mx, __shfl_xor_sync(0xffffffffu, mx, 1));
            mx = fmaxf(mx, __shfl_xor_sync(0xffffffffu, mx, 2));
            float mn = fmaxf(m_run[rr], mx);
            float sc = __expf(m_run[rr] - mn);
            float ps = 0.f, pu = 0.f;
            float* Srow = S + (size_t)row * N + q0 + ((lane & 3) << 1);
#pragma unroll
            for (int nt = 0; nt < 16; nt++) {
                float v0 = acc[nt][rr * 2], v1 = acc[nt][rr * 2 + 1];
                float2 u2 = __ldg((const float2*)(uptr + q0 + nt * 8 + ((lane & 3) << 1)));
                float p0 = __expf(v0 - mn), p1 = __expf(v1 - mn);
                ps += p0 + p1;
                pu += p0 * u2.x + p1 * u2.y;
                *(float2*)(Srow + nt * 8) = make_float2(v0, v1);
            }
            ps += __shfl_xor_sync(0xffffffffu, ps, 1);
            ps += __shfl_xor_sync(0xffffffffu, ps, 2);
            pu += __shfl_xor_sync(0xffffffffu, pu, 1);
            pu += __shfl_xor_sync(0xffffffffu, pu, 2);
            s_run[rr] = s_run[rr] * sc + ps;
            t_run[rr] = t_run[rr] * sc + pu;
            m_run[rr] = mn;
        }
    }

    if ((lane & 3) == 0) {
#pragma unroll
        for (int rr = 0; rr < 2; rr++) {
            int e = e0 + w * 16 + (lane >> 2) + rr * 8;
            g_rm[d][b][e] = m_run[rr];
            g_rs[d][b][e] = s_run[rr];
            float zv = t_run[rr] / s_run[rr];
            out[(size_t)d * (BATCH * N) + (size_t)b * N + e] = 1.f / (1.f + __expf(-zv));
        }
    }
}

// ---------------- K3: normalize + transpose-write A ----------------
__global__ void __launch_bounds__(256) k_norm_t(float* __restrict__ out) {
    __shared__ float T[64][65];
    int z = blockIdx.z, d = z >> 1, b = z & 1;
    const float* S  = g_S[d][b];
    const float* rm = g_rm[d][b];
    const float* rs = g_rs[d][b];
    float* Aout = out + 16384 + (size_t)d * (size_t)BATCH * N * N + (size_t)b * (size_t)N * N;
    int e0 = blockIdx.y * 64, q0 = blockIdx.x * 64;
    int t = threadIdx.x;

#pragma unroll
    for (int it = 0; it < 4; it++) {
        int e  = (t >> 4) + it * 16;
        int q4 = (t & 15) * 4;
        float4 v = *(const float4*)(S + (size_t)(e0 + e) * N + q0 + q4);
        float m    = rm[e0 + e];
        float rinv = __frcp_rn(rs[e0 + e]);
        T[e][q4 + 0] = __expf(v.x - m) * rinv;
        T[e][q4 + 1] = __expf(v.y - m) * rinv;
        T[e][q4 + 2] = __expf(v.z - m) * rinv;
        T[e][q4 + 3] = __expf(v.w - m) * rinv;
    }
    __syncthreads();
#pragma unroll
    for (int it = 0; it < 4; it++) {
        int q  = (t >> 4) + it * 16;
        int e4 = (t & 15) * 4;
        float4 o;
        o.x = T[e4 + 0][q];
        o.y = T[e4 + 1][q];
        o.z = T[e4 + 2][q];
        o.w = T[e4 + 3][q];
        *(float4*)(Aout + (size_t)(q0 + q) * N + e0 + e4) = o;
    }
}

// ---------------- launch ----------------
extern "C" void kernel_launch(void* const* d_in, const int* in_sizes, int n_in,
                              void* d_out, int out_size) {
    const float* ex   = (const float*)d_in[0];
    const float* qf   = (const float*)d_in[1];
    const float* Wex  = (const float*)d_in[2];
    const float* Wq   = (const float*)d_in[3];
    const float* gate = (const float*)d_in[4];
    float* out = (float*)d_out;

    cudaFuncSetAttribute(k_attn_mma, cudaFuncAttributeMaxDynamicSharedMemorySize, SMEM_TOT);

    k_transpose<<<dim3(256, 2), 256>>>(Wex, Wq);
    k_u        <<<dim3(N / 256, BATCH, 2), 256>>>(ex, qf, gate);
    k_bfrag    <<<dim3(N / 64, C / 64, 4), 256>>>(ex, qf);
    k_mproj    <<<dim3(N / TN, C / TM, 4), 256>>>(ex, qf);
    k_attn_mma <<<dim3(32, BATCH, 2), 256, SMEM_TOT>>>(out);
    k_norm_t   <<<dim3(N / 64, N / 64, 4), 256>>>(out);
}

// round 5
// speedup vs baseline: 3.0758x; 1.0034x over previous
#include <cuda_runtime.h>
#include <cuda_bf16.h>
#include <math_constants.h>
#include <cstdint>

#define BATCH 2
#define C 256
#define N 4096
#define KCH 16
#define TM 64
#define TN 128

typedef unsigned long long ull_t;

// ---------------- device scratch ----------------
__device__ float g_Wt[2][C * C];
__device__ float g_S[2][BATCH][N * N];          // p = exp(v - m_tile) spill
__device__ float g_u[2][BATCH][N];
__device__ float g_rm[2][BATCH][N];
__device__ float g_rs[2][BATCH][N];
__device__ float g_mt[2][BATCH][32][N];         // per-tile running max used at spill time
// A fragments (uint = bf16x2 pair along k), per (d,b): [mtile(256)][kstep(16)][lane(32)][r(4)]
__device__ uint32_t g_Afh[2 * BATCH * 524288];
__device__ uint32_t g_Afl[2 * BATCH * 524288];
// B fragments interleaved hi/lo: per (src,b): [ntile(512)][kstep(16)][lane(32)][4]
//   word0 = hi pair (k>>3)=0, word1 = hi pair (k>>3)=1, word2/3 = lo pairs
__device__ uint32_t g_Bf[2 * BATCH * 1048576];

union F4U { float4 f; ull_t u[2]; float s[4]; };

__device__ __forceinline__ void fma2(ull_t& d, ull_t a, ull_t b) {
    asm("fma.rn.f32x2 %0, %1, %2, %0;" : "+l"(d) : "l"(a), "l"(b));
}
__device__ __forceinline__ float lo2(ull_t x) { return __uint_as_float((unsigned)x); }
__device__ __forceinline__ float hi2(ull_t x) { return __uint_as_float((unsigned)(x >> 32)); }

__device__ __forceinline__ void bf16split(float v, unsigned short& h, unsigned short& l) {
    __nv_bfloat16 hb = __float2bfloat16_rn(v);
    float lr = v - __bfloat162float(hb);
    h = __bfloat16_as_ushort(hb);
    l = __bfloat16_as_ushort(__float2bfloat16_rn(lr));
}

__device__ __forceinline__ uint32_t awoff(int m, int k) {
    uint32_t mtile = m >> 4, kstep = k >> 4;
    uint32_t lane = ((m & 7) << 2) | ((k & 7) >> 1);
    uint32_t r = ((m >> 3) & 1) | (((k >> 3) & 1) << 1);
    return ((mtile * 16 + kstep) << 7) + (lane << 2) + r;
}
// interleaved B word offset: hi at +r, lo at +2+r
__device__ __forceinline__ uint32_t bwoff_i(int n, int k) {
    uint32_t ntile = n >> 3, kstep = k >> 4;
    uint32_t lane = ((n & 7) << 2) | ((k & 7) >> 1);
    uint32_t r = (k >> 3) & 1;
    return (((ntile * 16 + kstep) * 32 + lane) << 2) + r;
}

__device__ __forceinline__ void mma_bf16(float* c, const uint32_t* a, uint32_t b0, uint32_t b1) {
    asm volatile(
        "mma.sync.aligned.m16n8k16.row.col.f32.bf16.bf16.f32 "
        "{%0,%1,%2,%3}, {%4,%5,%6,%7}, {%8,%9}, {%0,%1,%2,%3};"
        : "+f"(c[0]), "+f"(c[1]), "+f"(c[2]), "+f"(c[3])
        : "r"(a[0]), "r"(a[1]), "r"(a[2]), "r"(a[3]), "r"(b0), "r"(b1));
}

// ---------------- K0: transpose weights ----------------
__global__ void k_transpose(const float* __restrict__ Wex, const float* __restrict__ Wq) {
    int d = blockIdx.y;
    const float* W = d ? Wq : Wex;
    int idx = blockIdx.x * 256 + threadIdx.x;
    int c = idx >> 8, cp = idx & 255;
    g_Wt[d][cp * C + c] = W[idx];
}

// ---------------- Ku ----------------
__global__ void k_u(const float* __restrict__ ex, const float* __restrict__ qf,
                    const float* __restrict__ gate) {
    __shared__ float gs[C];
    int d = blockIdx.z, b = blockIdx.y;
    gs[threadIdx.x] = gate[threadIdx.x];
    __syncthreads();
    const float* X = (d == 0 ? ex : qf) + (size_t)b * C * N;
    int j = blockIdx.x * 256 + threadIdx.x;
    float acc = 0.f;
#pragma unroll 8
    for (int c = 0; c < C; c++) acc += gs[c] * X[(size_t)c * N + j];
    g_u[d][b][j] = acc;
}

// ---------------- k_bfrag: X[c][n] -> interleaved B fragments ----------------
__global__ void __launch_bounds__(256) k_bfrag(const float* __restrict__ ex,
                                               const float* __restrict__ qf) {
    __shared__ float T[64][65];
    int z = blockIdx.z, src = z >> 1, b = z & 1;
    const float* X = (src == 0 ? ex : qf) + (size_t)b * C * N;
    int c0 = blockIdx.y * 64, n0 = blockIdx.x * 64;
    int t = threadIdx.x;
#pragma unroll
    for (int it = 0; it < 4; it++) {
        int c = (t >> 4) + it * 16;
        int n4 = (t & 15) * 4;
        float4 v = *(const float4*)(X + (size_t)(c0 + c) * N + n0 + n4);
        T[c][n4 + 0] = v.x; T[c][n4 + 1] = v.y; T[c][n4 + 2] = v.z; T[c][n4 + 3] = v.w;
    }
    __syncthreads();
    uint32_t bb = (uint32_t)(src * BATCH + b) * 1048576u;
#pragma unroll
    for (int it = 0; it < 4; it++) {
        int nl = (t >> 4) + it * 16;
        int c4 = (t & 15) * 4;
        int n = n0 + nl;
        unsigned short h[4], l[4];
#pragma unroll
        for (int k = 0; k < 4; k++) bf16split(T[c4 + k][nl], h[k], l[k]);
        int cg = c0 + c4;
        uint32_t w0 = bwoff_i(n, cg);            // pair (cg, cg+1)
        uint32_t w1 = bwoff_i(n, cg + 2);        // pair (cg+2, cg+3) = w0 + 4
        g_Bf[bb + w0]     = (uint32_t)h[0] | ((uint32_t)h[1] << 16);
        g_Bf[bb + w0 + 2] = (uint32_t)l[0] | ((uint32_t)l[1] << 16);
        g_Bf[bb + w1]     = (uint32_t)h[2] | ((uint32_t)h[3] << 16);
        g_Bf[bb + w1 + 2] = (uint32_t)l[2] | ((uint32_t)l[3] << 16);
    }
}

// ---------------- K1: M projection GEMM (f32x2) -> A fragments ----------------
__global__ void __launch_bounds__(256, 3) k_mproj(const float* __restrict__ ex,
                                                  const float* __restrict__ qf) {
    __shared__ float As2[2][KCH][TM * 2];
    __shared__ float Bs[2][KCH][TN];
    int z = blockIdx.z, d = z >> 1, b = z & 1;
    const float* A  = g_Wt[d];
    const float* Bm = (d == 0 ? ex : qf) + (size_t)b * C * N;
    int m0 = blockIdx.y * TM;
    int n0 = blockIdx.x * TN;

    const int t = threadIdx.x;
    const int ka = t >> 4, ca4 = (t & 15) * 4;
    const int kb = t >> 5, cb4 = (t & 31) * 4;
    const int ty = t >> 4, tx = t & 15;

    ull_t accp[4][4];
#pragma unroll
    for (int i = 0; i < 4; i++)
#pragma unroll
        for (int j = 0; j < 4; j++) accp[i][j] = 0ull;

    float4 av  = *(const float4*)(A + (size_t)ka * C + m0 + ca4);
    float4 bv0 = *(const float4*)(Bm + (size_t)kb * N + n0 + cb4);
    float4 bv1 = *(const float4*)(Bm + (size_t)(kb + 8) * N + n0 + cb4);
    {
        F4U d0, d1;
        d0.s[0] = av.x; d0.s[1] = av.x; d0.s[2] = av.y; d0.s[3] = av.y;
        d1.s[0] = av.z; d1.s[1] = av.z; d1.s[2] = av.w; d1.s[3] = av.w;
        *(float4*)&As2[0][ka][ca4 * 2]     = d0.f;
        *(float4*)&As2[0][ka][ca4 * 2 + 4] = d1.f;
        *(float4*)&Bs[0][kb][cb4]     = bv0;
        *(float4*)&Bs[0][kb + 8][cb4] = bv1;
    }
    __syncthreads();

    int buf = 0;
    for (int kc = 0; kc < C; kc += KCH) {
        bool more = (kc + KCH) < C;
        if (more) {
            av  = *(const float4*)(A + (size_t)(kc + KCH + ka) * C + m0 + ca4);
            bv0 = *(const float4*)(Bm + (size_t)(kc + KCH + kb) * N + n0 + cb4);
            bv1 = *(const float4*)(Bm + (size_t)(kc + KCH + kb + 8) * N + n0 + cb4);
        }
#pragma unroll
        for (int k = 0; k < KCH; k++) {
            F4U af0, af1, bf0, bf1;
            af0.f = *(const float4*)&As2[buf][k][ty * 8];
            af1.f = *(const float4*)&As2[buf][k][ty * 8 + 4];
            bf0.f = *(const float4*)&Bs[buf][k][tx * 4];
            bf1.f = *(const float4*)&Bs[buf][k][64 + tx * 4];
            ull_t ar0 = af0.u[0], ar1 = af0.u[1], ar2 = af1.u[0], ar3 = af1.u[1];
            ull_t bp0 = bf0.u[0], bp1 = bf0.u[1], bp2 = bf1.u[0], bp3 = bf1.u[1];
            fma2(accp[0][0], ar0, bp0); fma2(accp[0][1], ar0, bp1);
            fma2(accp[0][2], ar0, bp2); fma2(accp[0][3], ar0, bp3);
            fma2(accp[1][0], ar1, bp0); fma2(accp[1][1], ar1, bp1);
            fma2(accp[1][2], ar1, bp2); fma2(accp[1][3], ar1, bp3);
            fma2(accp[2][0], ar2, bp0); fma2(accp[2][1], ar2, bp1);
            fma2(accp[2][2], ar2, bp2); fma2(accp[2][3], ar2, bp3);
            fma2(accp[3][0], ar3, bp0); fma2(accp[3][1], ar3, bp1);
            fma2(accp[3][2], ar3, bp2); fma2(accp[3][3], ar3, bp3);
        }
        if (more) {
            F4U d0, d1;
            d0.s[0] = av.x; d0.s[1] = av.x; d0.s[2] = av.y; d0.s[3] = av.y;
            d1.s[0] = av.z; d1.s[1] = av.z; d1.s[2] = av.w; d1.s[3] = av.w;
            *(float4*)&As2[buf ^ 1][ka][ca4 * 2]     = d0.f;
            *(float4*)&As2[buf ^ 1][ka][ca4 * 2 + 4] = d1.f;
            *(float4*)&Bs[buf ^ 1][kb][cb4]     = bv0;
            *(float4*)&Bs[buf ^ 1][kb + 8][cb4] = bv1;
        }
        __syncthreads();
        buf ^= 1;
    }

    uint32_t ab = (uint32_t)(d * BATCH + b) * 524288u;
    int k0 = m0 + ty * 4;
#pragma unroll
    for (int jj = 0; jj < 8; jj++) {
        int jp = jj >> 1;
        float vv[4];
        if (jj & 1) { vv[0] = hi2(accp[0][jp]); vv[1] = hi2(accp[1][jp]); vv[2] = hi2(accp[2][jp]); vv[3] = hi2(accp[3][jp]); }
        else        { vv[0] = lo2(accp[0][jp]); vv[1] = lo2(accp[1][jp]); vv[2] = lo2(accp[2][jp]); vv[3] = lo2(accp[3][jp]); }
        int pos = n0 + ((jj < 4) ? (tx * 4 + jj) : (64 + tx * 4 + (jj - 4)));
        unsigned short h[4], l[4];
#pragma unroll
        for (int i = 0; i < 4; i++) bf16split(vv[i], h[i], l[i]);
        uint32_t w0 = awoff(pos, k0), w1 = awoff(pos, k0 + 2);
        g_Afh[ab + w0] = (uint32_t)h[0] | ((uint32_t)h[1] << 16);
        g_Afh[ab + w1] = (uint32_t)h[2] | ((uint32_t)h[3] << 16);
        g_Afl[ab + w0] = (uint32_t)l[0] | ((uint32_t)l[1] << 16);
        g_Afl[ab + w1] = (uint32_t)l[2] | ((uint32_t)l[3] << 16);
    }
}

// ---------------- K2: HMMA logits GEMM + online softmax, spills p ----------------
#define OFF_AFH 0
#define OFF_AFL 65536
#define OFF_BS  131072
#define SMEM_TOT 196608

__global__ void __launch_bounds__(256, 1) k_attn_mma(float* __restrict__ out) {
    extern __shared__ char smc[];
    uint32_t* Afh = (uint32_t*)(smc + OFF_AFH);
    uint32_t* Afl = (uint32_t*)(smc + OFF_AFL);
    uint4*    Bs4 = (uint4*)(smc + OFF_BS);       // [2][2048] uint4

    int tid = threadIdx.x, w = tid >> 5, lane = tid & 31;
    int panel = blockIdx.x, b = blockIdx.y, d = blockIdx.z;
    int e0 = panel * 128;
    int src = (d == 0) ? 1 : 0;

    const uint32_t* Agh = g_Afh + (size_t)(d * BATCH + b) * 524288 + (size_t)panel * 16384;
    const uint32_t* Agl = g_Afl + (size_t)(d * BATCH + b) * 524288 + (size_t)panel * 16384;
    const uint4* Bg = (const uint4*)g_Bf + (size_t)(src * BATCH + b) * 262144;
    const float* uptr = g_u[d][b];
    float* S = g_S[d][b];

#pragma unroll
    for (int i = 0; i < 16; i++) {
        int j = tid + i * 256;
        ((uint4*)Afh)[j] = __ldg((const uint4*)Agh + j);
        ((uint4*)Afl)[j] = __ldg((const uint4*)Agl + j);
    }

    // prefetch B chunk 0 (tile 0, kc 0): 2048 uint4
    uint4 pf[8];
#pragma unroll
    for (int i = 0; i < 8; i++) {
        int j = tid + i * 256;
        int ln = j & 31, ks = (j >> 5) & 3, ntl = j >> 7;
        pf[i] = __ldg(Bg + ((size_t)(0 * 16 + ntl) * 16 + 0 * 4 + ks) * 32 + ln);
    }
#pragma unroll
    for (int i = 0; i < 8; i++) Bs4[tid + i * 256] = pf[i];
    __syncthreads();

    float m_run[2], s_run[2], t_run[2];
    m_run[0] = m_run[1] = -CUDART_INF_F;
    s_run[0] = s_run[1] = 0.f;
    t_run[0] = t_run[1] = 0.f;

    int buf = 0;
    for (int tile = 0; tile < 32; tile++) {
        float acc[16][4];
#pragma unroll
        for (int nt = 0; nt < 16; nt++)
#pragma unroll
            for (int r = 0; r < 4; r++) acc[nt][r] = 0.f;

        for (int kc = 0; kc < 4; kc++) {
            int gc = tile * 4 + kc;
            bool more = (gc + 1) < 128;
            if (more) {
                int tile2 = (gc + 1) >> 2, kc2 = (gc + 1) & 3;
#pragma unroll
                for (int i = 0; i < 8; i++) {
                    int j = tid + i * 256;
                    int ln = j & 31, ks = (j >> 5) & 3, ntl = j >> 7;
                    pf[i] = __ldg(Bg + ((size_t)(tile2 * 16 + ntl) * 16 + kc2 * 4 + ks) * 32 + ln);
                }
            }
#pragma unroll
            for (int ks = 0; ks < 4; ks++) {
                int kstep = kc * 4 + ks;
                uint32_t ah[4], al[4];
                *(uint4*)ah = *(const uint4*)(Afh + ((w * 16 + kstep) << 7) + (lane << 2));
                *(uint4*)al = *(const uint4*)(Afl + ((w * 16 + kstep) << 7) + (lane << 2));
#pragma unroll
                for (int nt = 0; nt < 16; nt++) {
                    uint4 bf = Bs4[buf * 2048 + ((nt * 4 + ks) << 5) + lane];
                    mma_bf16(acc[nt], ah, bf.x, bf.y);   // hi*hi
                    mma_bf16(acc[nt], ah, bf.z, bf.w);   // hi*lo
                    mma_bf16(acc[nt], al, bf.x, bf.y);   // lo*hi
                }
            }
            if (more) {
#pragma unroll
                for (int i = 0; i < 8; i++) Bs4[(buf ^ 1) * 2048 + tid + i * 256] = pf[i];
            }
            __syncthreads();
            buf ^= 1;
        }

        int q0 = tile * 128;
#pragma unroll
        for (int rr = 0; rr < 2; rr++) {
            int row = e0 + w * 16 + (lane >> 2) + rr * 8;
            float mx = -CUDART_INF_F;
#pragma unroll
            for (int nt = 0; nt < 16; nt++)
                mx = fmaxf(mx, fmaxf(acc[nt][rr * 2], acc[nt][rr * 2 + 1]));
            mx = fmaxf(mx, __shfl_xor_sync(0xffffffffu, mx, 1));
            mx = fmaxf(mx, __shfl_xor_sync(0xffffffffu, mx, 2));
            float mn = fmaxf(m_run[rr], mx);
            float sc = __expf(m_run[rr] - mn);
            float ps = 0.f, pu = 0.f;
            float* Srow = S + (size_t)row * N + q0 + ((lane & 3) << 1);
#pragma unroll
            for (int nt = 0; nt < 16; nt++) {
                float v0 = acc[nt][rr * 2], v1 = acc[nt][rr * 2 + 1];
                float2 u2 = __ldg((const float2*)(uptr + q0 + nt * 8 + ((lane & 3) << 1)));
                float p0 = __expf(v0 - mn), p1 = __expf(v1 - mn);
                ps += p0 + p1;
                pu += p0 * u2.x + p1 * u2.y;
                *(float2*)(Srow + nt * 8) = make_float2(p0, p1);   // spill p, not v
            }
            ps += __shfl_xor_sync(0xffffffffu, ps, 1);
            ps += __shfl_xor_sync(0xffffffffu, ps, 2);
            pu += __shfl_xor_sync(0xffffffffu, pu, 1);
            pu += __shfl_xor_sync(0xffffffffu, pu, 2);
            s_run[rr] = s_run[rr] * sc + ps;
            t_run[rr] = t_run[rr] * sc + pu;
            m_run[rr] = mn;
            if ((lane & 3) == 0) g_mt[d][b][tile][row] = mn;
        }
    }

    if ((lane & 3) == 0) {
#pragma unroll
        for (int rr = 0; rr < 2; rr++) {
            int e = e0 + w * 16 + (lane >> 2) + rr * 8;
            g_rm[d][b][e] = m_run[rr];
            g_rs[d][b][e] = s_run[rr];
            float zv = t_run[rr] / s_run[rr];
            out[(size_t)d * (BATCH * N) + (size_t)b * N + e] = 1.f / (1.f + __expf(-zv));
        }
    }
}

// ---------------- K3: rescale + transpose-write A (no bulk exp) ----------------
__global__ void __launch_bounds__(256) k_norm_t(float* __restrict__ out) {
    __shared__ float T[64][65];
    __shared__ float fs[64];
    int z = blockIdx.z, d = z >> 1, b = z & 1;
    const float* S  = g_S[d][b];
    const float* rm = g_rm[d][b];
    const float* rs = g_rs[d][b];
    float* Aout = out + 16384 + (size_t)d * (size_t)BATCH * N * N + (size_t)b * (size_t)N * N;
    int e0 = blockIdx.y * 64, q0 = blockIdx.x * 64;
    int tile = q0 >> 7;
    int t = threadIdx.x;

    if (t < 64) {
        int e = e0 + t;
        fs[t] = __expf(g_mt[d][b][tile][e] - rm[e]) * __frcp_rn(rs[e]);
    }
    __syncthreads();

#pragma unroll
    for (int it = 0; it < 4; it++) {
        int e  = (t >> 4) + it * 16;
        int q4 = (t & 15) * 4;
        float4 v = *(const float4*)(S + (size_t)(e0 + e) * N + q0 + q4);
        float f = fs[e];
        T[e][q4 + 0] = v.x * f;
        T[e][q4 + 1] = v.y * f;
        T[e][q4 + 2] = v.z * f;
        T[e][q4 + 3] = v.w * f;
    }
    __syncthreads();
#pragma unroll
    for (int it = 0; it < 4; it++) {
        int q  = (t >> 4) + it * 16;
        int e4 = (t & 15) * 4;
        float4 o;
        o.x = T[e4 + 0][q];
        o.y = T[e4 + 1][q];
        o.z = T[e4 + 2][q];
        o.w = T[e4 + 3][q];
        *(float4*)(Aout + (size_t)(q0 + q) * N + e0 + e4) = o;
    }
}

// ---------------- launch ----------------
extern "C" void kernel_launch(void* const* d_in, const int* in_sizes, int n_in,
                              void* d_out, int out_size) {
    const float* ex   = (const float*)d_in[0];
    const float* qf   = (const float*)d_in[1];
    const float* Wex  = (const float*)d_in[2];
    const float* Wq   = (const float*)d_in[3];
    const float* gate = (const float*)d_in[4];
    float* out = (float*)d_out;

    cudaFuncSetAttribute(k_attn_mma, cudaFuncAttributeMaxDynamicSharedMemorySize, SMEM_TOT);

    k_transpose<<<dim3(256, 2), 256>>>(Wex, Wq);
    k_u        <<<dim3(N / 256, BATCH, 2), 256>>>(ex, qf, gate);
    k_bfrag    <<<dim3(N / 64, C / 64, 4), 256>>>(ex, qf);
    k_mproj    <<<dim3(N / TN, C / TM, 4), 256>>>(ex, qf);
    k_attn_mma <<<dim3(32, BATCH, 2), 256, SMEM_TOT>>>(out);
    k_norm_t   <<<dim3(N / 64, N / 64, 4), 256>>>(out);
}

// round 6
// speedup vs baseline: 3.3895x; 1.1020x over previous
#include <cuda_runtime.h>
#include <cuda_bf16.h>
#include <cuda_fp16.h>
#include <math_constants.h>
#include <cstdint>

#define BATCH 2
#define C 256
#define N 4096
#define KCH 16
#define TM 64
#define TN 128

typedef unsigned long long ull_t;

// ---------------- device scratch ----------------
__device__ float g_Wt[2][C * C];
__device__ __half g_S[2][BATCH][N * N];         // p = exp(v - m_tile) spill (fp16)
__device__ float g_u[2][BATCH][N];
__device__ float g_rm[2][BATCH][N];
__device__ float g_rs[2][BATCH][N];
__device__ float g_mt[2][BATCH][64][N];         // per-64col-tile running max at spill time
// A fragments, per (d,b): [mtile(256)][kstep(16)][lane(32)][r(4)]
__device__ uint32_t g_Afh[2 * BATCH * 524288];
__device__ uint32_t g_Afl[2 * BATCH * 524288];
// B fragments interleaved hi/lo: per (src,b): [ntile(512)][kstep(16)][lane(32)][4]
__device__ uint32_t g_Bf[2 * BATCH * 1048576];

union F4U { float4 f; ull_t u[2]; float s[4]; };

__device__ __forceinline__ void fma2(ull_t& d, ull_t a, ull_t b) {
    asm("fma.rn.f32x2 %0, %1, %2, %0;" : "+l"(d) : "l"(a), "l"(b));
}
__device__ __forceinline__ float lo2(ull_t x) { return __uint_as_float((unsigned)x); }
__device__ __forceinline__ float hi2(ull_t x) { return __uint_as_float((unsigned)(x >> 32)); }

__device__ __forceinline__ void bf16split(float v, unsigned short& h, unsigned short& l) {
    __nv_bfloat16 hb = __float2bfloat16_rn(v);
    float lr = v - __bfloat162float(hb);
    h = __bfloat16_as_ushort(hb);
    l = __bfloat16_as_ushort(__float2bfloat16_rn(lr));
}

__device__ __forceinline__ uint32_t awoff(int m, int k) {
    uint32_t mtile = m >> 4, kstep = k >> 4;
    uint32_t lane = ((m & 7) << 2) | ((k & 7) >> 1);
    uint32_t r = ((m >> 3) & 1) | (((k >> 3) & 1) << 1);
    return ((mtile * 16 + kstep) << 7) + (lane << 2) + r;
}
__device__ __forceinline__ uint32_t bwoff_i(int n, int k) {
    uint32_t ntile = n >> 3, kstep = k >> 4;
    uint32_t lane = ((n & 7) << 2) | ((k & 7) >> 1);
    uint32_t r = (k >> 3) & 1;
    return (((ntile * 16 + kstep) * 32 + lane) << 2) + r;
}

__device__ __forceinline__ void mma_bf16(float* c, const uint32_t* a, uint32_t b0, uint32_t b1) {
    asm volatile(
        "mma.sync.aligned.m16n8k16.row.col.f32.bf16.bf16.f32 "
        "{%0,%1,%2,%3}, {%4,%5,%6,%7}, {%8,%9}, {%0,%1,%2,%3};"
        : "+f"(c[0]), "+f"(c[1]), "+f"(c[2]), "+f"(c[3])
        : "r"(a[0]), "r"(a[1]), "r"(a[2]), "r"(a[3]), "r"(b0), "r"(b1));
}

// ---------------- K0: transpose weights ----------------
__global__ void k_transpose(const float* __restrict__ Wex, const float* __restrict__ Wq) {
    int d = blockIdx.y;
    const float* W = d ? Wq : Wex;
    int idx = blockIdx.x * 256 + threadIdx.x;
    int c = idx >> 8, cp = idx & 255;
    g_Wt[d][cp * C + c] = W[idx];
}

// ---------------- Ku ----------------
__global__ void k_u(const float* __restrict__ ex, const float* __restrict__ qf,
                    const float* __restrict__ gate) {
    __shared__ float gs[C];
    int d = blockIdx.z, b = blockIdx.y;
    gs[threadIdx.x] = gate[threadIdx.x];
    __syncthreads();
    const float* X = (d == 0 ? ex : qf) + (size_t)b * C * N;
    int j = blockIdx.x * 256 + threadIdx.x;
    float acc = 0.f;
#pragma unroll 8
    for (int c = 0; c < C; c++) acc += gs[c] * X[(size_t)c * N + j];
    g_u[d][b][j] = acc;
}

// ---------------- k_bfrag ----------------
__global__ void __launch_bounds__(256) k_bfrag(const float* __restrict__ ex,
                                               const float* __restrict__ qf) {
    __shared__ float T[64][65];
    int z = blockIdx.z, src = z >> 1, b = z & 1;
    const float* X = (src == 0 ? ex : qf) + (size_t)b * C * N;
    int c0 = blockIdx.y * 64, n0 = blockIdx.x * 64;
    int t = threadIdx.x;
#pragma unroll
    for (int it = 0; it < 4; it++) {
        int c = (t >> 4) + it * 16;
        int n4 = (t & 15) * 4;
        float4 v = *(const float4*)(X + (size_t)(c0 + c) * N + n0 + n4);
        T[c][n4 + 0] = v.x; T[c][n4 + 1] = v.y; T[c][n4 + 2] = v.z; T[c][n4 + 3] = v.w;
    }
    __syncthreads();
    uint32_t bb = (uint32_t)(src * BATCH + b) * 1048576u;
#pragma unroll
    for (int it = 0; it < 4; it++) {
        int nl = (t >> 4) + it * 16;
        int c4 = (t & 15) * 4;
        int n = n0 + nl;
        unsigned short h[4], l[4];
#pragma unroll
        for (int k = 0; k < 4; k++) bf16split(T[c4 + k][nl], h[k], l[k]);
        int cg = c0 + c4;
        uint32_t w0 = bwoff_i(n, cg);
        uint32_t w1 = bwoff_i(n, cg + 2);
        g_Bf[bb + w0]     = (uint32_t)h[0] | ((uint32_t)h[1] << 16);
        g_Bf[bb + w0 + 2] = (uint32_t)l[0] | ((uint32_t)l[1] << 16);
        g_Bf[bb + w1]     = (uint32_t)h[2] | ((uint32_t)h[3] << 16);
        g_Bf[bb + w1 + 2] = (uint32_t)l[2] | ((uint32_t)l[3] << 16);
    }
}

// ---------------- K1: M projection GEMM (f32x2) -> A fragments ----------------
__global__ void __launch_bounds__(256, 3) k_mproj(const float* __restrict__ ex,
                                                  const float* __restrict__ qf) {
    __shared__ float As2[2][KCH][TM * 2];
    __shared__ float Bs[2][KCH][TN];
    int z = blockIdx.z, d = z >> 1, b = z & 1;
    const float* A  = g_Wt[d];
    const float* Bm = (d == 0 ? ex : qf) + (size_t)b * C * N;
    int m0 = blockIdx.y * TM;
    int n0 = blockIdx.x * TN;

    const int t = threadIdx.x;
    const int ka = t >> 4, ca4 = (t & 15) * 4;
    const int kb = t >> 5, cb4 = (t & 31) * 4;
    const int ty = t >> 4, tx = t & 15;

    ull_t accp[4][4];
#pragma unroll
    for (int i = 0; i < 4; i++)
#pragma unroll
        for (int j = 0; j < 4; j++) accp[i][j] = 0ull;

    float4 av  = *(const float4*)(A + (size_t)ka * C + m0 + ca4);
    float4 bv0 = *(const float4*)(Bm + (size_t)kb * N + n0 + cb4);
    float4 bv1 = *(const float4*)(Bm + (size_t)(kb + 8) * N + n0 + cb4);
    {
        F4U d0, d1;
        d0.s[0] = av.x; d0.s[1] = av.x; d0.s[2] = av.y; d0.s[3] = av.y;
        d1.s[0] = av.z; d1.s[1] = av.z; d1.s[2] = av.w; d1.s[3] = av.w;
        *(float4*)&As2[0][ka][ca4 * 2]     = d0.f;
        *(float4*)&As2[0][ka][ca4 * 2 + 4] = d1.f;
        *(float4*)&Bs[0][kb][cb4]     = bv0;
        *(float4*)&Bs[0][kb + 8][cb4] = bv1;
    }
    __syncthreads();

    int buf = 0;
    for (int kc = 0; kc < C; kc += KCH) {
        bool more = (kc + KCH) < C;
        if (more) {
            av  = *(const float4*)(A + (size_t)(kc + KCH + ka) * C + m0 + ca4);
            bv0 = *(const float4*)(Bm + (size_t)(kc + KCH + kb) * N + n0 + cb4);
            bv1 = *(const float4*)(Bm + (size_t)(kc + KCH + kb + 8) * N + n0 + cb4);
        }
#pragma unroll
        for (int k = 0; k < KCH; k++) {
            F4U af0, af1, bf0, bf1;
            af0.f = *(const float4*)&As2[buf][k][ty * 8];
            af1.f = *(const float4*)&As2[buf][k][ty * 8 + 4];
            bf0.f = *(const float4*)&Bs[buf][k][tx * 4];
            bf1.f = *(const float4*)&Bs[buf][k][64 + tx * 4];
            ull_t ar0 = af0.u[0], ar1 = af0.u[1], ar2 = af1.u[0], ar3 = af1.u[1];
            ull_t bp0 = bf0.u[0], bp1 = bf0.u[1], bp2 = bf1.u[0], bp3 = bf1.u[1];
            fma2(accp[0][0], ar0, bp0); fma2(accp[0][1], ar0, bp1);
            fma2(accp[0][2], ar0, bp2); fma2(accp[0][3], ar0, bp3);
            fma2(accp[1][0], ar1, bp0); fma2(accp[1][1], ar1, bp1);
            fma2(accp[1][2], ar1, bp2); fma2(accp[1][3], ar1, bp3);
            fma2(accp[2][0], ar2, bp0); fma2(accp[2][1], ar2, bp1);
            fma2(accp[2][2], ar2, bp2); fma2(accp[2][3], ar2, bp3);
            fma2(accp[3][0], ar3, bp0); fma2(accp[3][1], ar3, bp1);
            fma2(accp[3][2], ar3, bp2); fma2(accp[3][3], ar3, bp3);
        }
        if (more) {
            F4U d0, d1;
            d0.s[0] = av.x; d0.s[1] = av.x; d0.s[2] = av.y; d0.s[3] = av.y;
            d1.s[0] = av.z; d1.s[1] = av.z; d1.s[2] = av.w; d1.s[3] = av.w;
            *(float4*)&As2[buf ^ 1][ka][ca4 * 2]     = d0.f;
            *(float4*)&As2[buf ^ 1][ka][ca4 * 2 + 4] = d1.f;
            *(float4*)&Bs[buf ^ 1][kb][cb4]     = bv0;
            *(float4*)&Bs[buf ^ 1][kb + 8][cb4] = bv1;
        }
        __syncthreads();
        buf ^= 1;
    }

    uint32_t ab = (uint32_t)(d * BATCH + b) * 524288u;
    int k0 = m0 + ty * 4;
#pragma unroll
    for (int jj = 0; jj < 8; jj++) {
        int jp = jj >> 1;
        float vv[4];
        if (jj & 1) { vv[0] = hi2(accp[0][jp]); vv[1] = hi2(accp[1][jp]); vv[2] = hi2(accp[2][jp]); vv[3] = hi2(accp[3][jp]); }
        else        { vv[0] = lo2(accp[0][jp]); vv[1] = lo2(accp[1][jp]); vv[2] = lo2(accp[2][jp]); vv[3] = lo2(accp[3][jp]); }
        int pos = n0 + ((jj < 4) ? (tx * 4 + jj) : (64 + tx * 4 + (jj - 4)));
        unsigned short h[4], l[4];
#pragma unroll
        for (int i = 0; i < 4; i++) bf16split(vv[i], h[i], l[i]);
        uint32_t w0 = awoff(pos, k0), w1 = awoff(pos, k0 + 2);
        g_Afh[ab + w0] = (uint32_t)h[0] | ((uint32_t)h[1] << 16);
        g_Afh[ab + w1] = (uint32_t)h[2] | ((uint32_t)h[3] << 16);
        g_Afl[ab + w0] = (uint32_t)l[0] | ((uint32_t)l[1] << 16);
        g_Afl[ab + w1] = (uint32_t)l[2] | ((uint32_t)l[3] << 16);
    }
}

// ---------------- K2: HMMA logits GEMM + online softmax ----------------
// warp = 32 rows x 64 cols: rg = w&3 -> mtiles 2rg,2rg+1; set = w>>2 -> col half.
#define OFF_AFH 0
#define OFF_AFL 65536
#define OFF_BS  131072
#define SMEM_TOT 196608

__global__ void __launch_bounds__(256, 1) k_attn_mma(float* __restrict__ out) {
    extern __shared__ char smc[];
    uint32_t* Afh = (uint32_t*)(smc + OFF_AFH);
    uint32_t* Afl = (uint32_t*)(smc + OFF_AFL);
    uint4*    Bs4 = (uint4*)(smc + OFF_BS);       // [2][2048] uint4

    int tid = threadIdx.x, w = tid >> 5, lane = tid & 31;
    int rg = w & 3, set = w >> 2;
    int panel = blockIdx.x, b = blockIdx.y, d = blockIdx.z;
    int e0 = panel * 128;
    int src = (d == 0) ? 1 : 0;

    const uint32_t* Agh = g_Afh + (size_t)(d * BATCH + b) * 524288 + (size_t)panel * 16384;
    const uint32_t* Agl = g_Afl + (size_t)(d * BATCH + b) * 524288 + (size_t)panel * 16384;
    const uint4* Bg = (const uint4*)g_Bf + (size_t)(src * BATCH + b) * 262144;
    const float* uptr = g_u[d][b];
    __half* S = g_S[d][b];

#pragma unroll
    for (int i = 0; i < 16; i++) {
        int j = tid + i * 256;
        ((uint4*)Afh)[j] = __ldg((const uint4*)Agh + j);
        ((uint4*)Afl)[j] = __ldg((const uint4*)Agl + j);
    }

    uint4 pf[8];
#pragma unroll
    for (int i = 0; i < 8; i++) {
        int j = tid + i * 256;
        int ln = j & 31, ks = (j >> 5) & 3, ntl = j >> 7;
        pf[i] = __ldg(Bg + ((size_t)(0 * 16 + ntl) * 16 + 0 * 4 + ks) * 32 + ln);
    }
#pragma unroll
    for (int i = 0; i < 8; i++) Bs4[tid + i * 256] = pf[i];
    __syncthreads();

    // states: st = mt*2 + rr  (mt = local mtile 0/1, rr = row-half 0/1)
    float m_run[4], s_run[4], t_run[4];
#pragma unroll
    for (int i = 0; i < 4; i++) { m_run[i] = -CUDART_INF_F; s_run[i] = 0.f; t_run[i] = 0.f; }

    int buf = 0;
    for (int tile = 0; tile < 32; tile++) {
        float acc[2][8][4];
#pragma unroll
        for (int mt = 0; mt < 2; mt++)
#pragma unroll
            for (int nt = 0; nt < 8; nt++)
#pragma unroll
                for (int r = 0; r < 4; r++) acc[mt][nt][r] = 0.f;

        for (int kc = 0; kc < 4; kc++) {
            int gc = tile * 4 + kc;
            bool more = (gc + 1) < 128;
            if (more) {
                int tile2 = (gc + 1) >> 2, kc2 = (gc + 1) & 3;
#pragma unroll
                for (int i = 0; i < 8; i++) {
                    int j = tid + i * 256;
                    int ln = j & 31, ks = (j >> 5) & 3, ntl = j >> 7;
                    pf[i] = __ldg(Bg + ((size_t)(tile2 * 16 + ntl) * 16 + kc2 * 4 + ks) * 32 + ln);
                }
            }
#pragma unroll
            for (int ks = 0; ks < 4; ks++) {
                int kstep = kc * 4 + ks;
                uint32_t ah0[4], al0[4], ah1[4], al1[4];
                *(uint4*)ah0 = *(const uint4*)(Afh + (((rg * 2 + 0) * 16 + kstep) << 7) + (lane << 2));
                *(uint4*)al0 = *(const uint4*)(Afl + (((rg * 2 + 0) * 16 + kstep) << 7) + (lane << 2));
                *(uint4*)ah1 = *(const uint4*)(Afh + (((rg * 2 + 1) * 16 + kstep) << 7) + (lane << 2));
                *(uint4*)al1 = *(const uint4*)(Afl + (((rg * 2 + 1) * 16 + kstep) << 7) + (lane << 2));
#pragma unroll
                for (int j = 0; j < 8; j++) {
                    uint4 bf = Bs4[buf * 2048 + (((set * 8 + j) * 4 + ks) << 5) + lane];
                    mma_bf16(acc[0][j], ah0, bf.x, bf.y);
                    mma_bf16(acc[0][j], ah0, bf.z, bf.w);
                    mma_bf16(acc[0][j], al0, bf.x, bf.y);
                    mma_bf16(acc[1][j], ah1, bf.x, bf.y);
                    mma_bf16(acc[1][j], ah1, bf.z, bf.w);
                    mma_bf16(acc[1][j], al1, bf.x, bf.y);
                }
            }
            if (more) {
#pragma unroll
                for (int i = 0; i < 8; i++) Bs4[(buf ^ 1) * 2048 + tid + i * 256] = pf[i];
            }
            __syncthreads();
            buf ^= 1;
        }

        int qb = tile * 128 + set * 64;
        int t2 = tile * 2 + set;
#pragma unroll
        for (int mt = 0; mt < 2; mt++) {
#pragma unroll
            for (int rr = 0; rr < 2; rr++) {
                int st = mt * 2 + rr;
                int lrow = rg * 32 + mt * 16 + (lane >> 2) + rr * 8;
                int row = e0 + lrow;
                float mx = -CUDART_INF_F;
#pragma unroll
                for (int nt = 0; nt < 8; nt++)
                    mx = fmaxf(mx, fmaxf(acc[mt][nt][rr * 2], acc[mt][nt][rr * 2 + 1]));
                mx = fmaxf(mx, __shfl_xor_sync(0xffffffffu, mx, 1));
                mx = fmaxf(mx, __shfl_xor_sync(0xffffffffu, mx, 2));
                float mn = fmaxf(m_run[st], mx);
                float sc = __expf(m_run[st] - mn);
                float ps = 0.f, pu = 0.f;
                __half* Srow = S + (size_t)row * N + qb + ((lane & 3) << 1);
#pragma unroll
                for (int nt = 0; nt < 8; nt++) {
                    float v0 = acc[mt][nt][rr * 2], v1 = acc[mt][nt][rr * 2 + 1];
                    float2 u2 = __ldg((const float2*)(uptr + qb + nt * 8 + ((lane & 3) << 1)));
                    float p0 = __expf(v0 - mn), p1 = __expf(v1 - mn);
                    ps += p0 + p1;
                    pu += p0 * u2.x + p1 * u2.y;
                    *(__half2*)(Srow + nt * 8) = __floats2half2_rn(p0, p1);
                }
                ps += __shfl_xor_sync(0xffffffffu, ps, 1);
                ps += __shfl_xor_sync(0xffffffffu, ps, 2);
                pu += __shfl_xor_sync(0xffffffffu, pu, 1);
                pu += __shfl_xor_sync(0xffffffffu, pu, 2);
                s_run[st] = s_run[st] * sc + ps;
                t_run[st] = t_run[st] * sc + pu;
                m_run[st] = mn;
                if ((lane & 3) == 0) g_mt[d][b][t2][row] = mn;
            }
        }
    }

    // ---- merge the two column-half states per row ----
    float* mrg = (float*)(smc + OFF_BS);   // [128][3], B buffers dead now
    if (set == 1 && (lane & 3) == 0) {
#pragma unroll
        for (int st = 0; st < 4; st++) {
            int mt = st >> 1, rr = st & 1;
            int lrow = rg * 32 + mt * 16 + (lane >> 2) + rr * 8;
            mrg[lrow * 3 + 0] = m_run[st];
            mrg[lrow * 3 + 1] = s_run[st];
            mrg[lrow * 3 + 2] = t_run[st];
        }
    }
    __syncthreads();
    if (set == 0 && (lane & 3) == 0) {
#pragma unroll
        for (int st = 0; st < 4; st++) {
            int mt = st >> 1, rr = st & 1;
            int lrow = rg * 32 + mt * 16 + (lane >> 2) + rr * 8;
            int e = e0 + lrow;
            float m1 = mrg[lrow * 3 + 0];
            float s1 = mrg[lrow * 3 + 1];
            float t1 = mrg[lrow * 3 + 2];
            float mf = fmaxf(m_run[st], m1);
            float sc0 = __expf(m_run[st] - mf);
            float sc1 = __expf(m1 - mf);
            float sf = s_run[st] * sc0 + s1 * sc1;
            float tf = t_run[st] * sc0 + t1 * sc1;
            g_rm[d][b][e] = mf;
            g_rs[d][b][e] = sf;
            float zv = tf / sf;
            out[(size_t)d * (BATCH * N) + (size_t)b * N + e] = 1.f / (1.f + __expf(-zv));
        }
    }
}

// ---------------- K3: rescale + transpose-write A (fp16 p in, fp32 A out) ----------------
__global__ void __launch_bounds__(256) k_norm_t(float* __restrict__ out) {
    __shared__ float T[64][65];
    __shared__ float fs[64];
    int z = blockIdx.z, d = z >> 1, b = z & 1;
    const __half* S = g_S[d][b];
    const float* rm = g_rm[d][b];
    const float* rs = g_rs[d][b];
    float* Aout = out + 16384 + (size_t)d * (size_t)BATCH * N * N + (size_t)b * (size_t)N * N;
    int e0 = blockIdx.y * 64, q0 = blockIdx.x * 64;
    int t2 = blockIdx.x;          // 64-col tile index
    int t = threadIdx.x;

    if (t < 64) {
        int e = e0 + t;
        fs[t] = __expf(g_mt[d][b][t2][e] - rm[e]) * __frcp_rn(rs[e]);
    }
    __syncthreads();

#pragma unroll
    for (int it = 0; it < 4; it++) {
        int e  = (t >> 4) + it * 16;
        int q4 = (t & 15) * 4;
        uint2 rd = *(const uint2*)(S + (size_t)(e0 + e) * N + q0 + q4);
        float2 f0 = __half22float2(*(__half2*)&rd.x);
        float2 f1 = __half22float2(*(__half2*)&rd.y);
        float f = fs[e];
        T[e][q4 + 0] = f0.x * f;
        T[e][q4 + 1] = f0.y * f;
        T[e][q4 + 2] = f1.x * f;
        T[e][q4 + 3] = f1.y * f;
    }
    __syncthreads();
#pragma unroll
    for (int it = 0; it < 4; it++) {
        int q  = (t >> 4) + it * 16;
        int e4 = (t & 15) * 4;
        float4 o;
        o.x = T[e4 + 0][q];
        o.y = T[e4 + 1][q];
        o.z = T[e4 + 2][q];
        o.w = T[e4 + 3][q];
        *(float4*)(Aout + (size_t)(q0 + q) * N + e0 + e4) = o;
    }
}

// ---------------- launch ----------------
extern "C" void kernel_launch(void* const* d_in, const int* in_sizes, int n_in,
                              void* d_out, int out_size) {
    const float* ex   = (const float*)d_in[0];
    const float* qf   = (const float*)d_in[1];
    const float* Wex  = (const float*)d_in[2];
    const float* Wq   = (const float*)d_in[3];
    const float* gate = (const float*)d_in[4];
    float* out = (float*)d_out;

    cudaFuncSetAttribute(k_attn_mma, cudaFuncAttributeMaxDynamicSharedMemorySize, SMEM_TOT);

    k_transpose<<<dim3(256, 2), 256>>>(Wex, Wq);
    k_u        <<<dim3(N / 256, BATCH, 2), 256>>>(ex, qf, gate);
    k_bfrag    <<<dim3(N / 64, C / 64, 4), 256>>>(ex, qf);
    k_mproj    <<<dim3(N / TN, C / TM, 4), 256>>>(ex, qf);
    k_attn_mma <<<dim3(32, BATCH, 2), 256, SMEM_TOT>>>(out);
    k_norm_t   <<<dim3(N / 64, N / 64, 4), 256>>>(out);
}

// round 7
// speedup vs baseline: 3.6838x; 1.0868x over previous
#include <cuda_runtime.h>
#include <cuda_bf16.h>
#include <cuda_fp16.h>
#include <math_constants.h>
#include <cstdint>

#define BATCH 2
#define C 256
#define N 4096

typedef unsigned long long ull_t;

// ---------------- device scratch ----------------
__device__ __half g_S[2][BATCH][N * N];         // p = exp(v - m_tile) spill (fp16)
__device__ float g_u[2][BATCH][N];
__device__ float g_rm[2][BATCH][N];
__device__ float g_rs[2][BATCH][N];
__device__ float g_mt[2][BATCH][64][N];         // per-64col-tile running max at spill time
// A fragments of Mt (attn A operand), per (d,b): [mtile(256)][kstep(16)][lane(32)][r(4)]
__device__ uint32_t g_Afh[2 * BATCH * 524288];
__device__ uint32_t g_Afl[2 * BATCH * 524288];
// B fragments of X interleaved hi/lo: per (src,b): [ntile(512)][kstep(16)][lane(32)][4]
__device__ uint32_t g_Bf[2 * BATCH * 1048576];
// A fragments of X (mproj2 A operand), per (src,b) like g_Af
__device__ uint32_t g_XAh[2 * BATCH * 524288];
__device__ uint32_t g_XAl[2 * BATCH * 524288];
// B fragments of W interleaved hi/lo, per dir: [ntile(32)][kstep(16)][lane(32)][4]
__device__ uint32_t g_Wf[2 * 65536];

__device__ __forceinline__ void bf16split(float v, unsigned short& h, unsigned short& l) {
    __nv_bfloat16 hb = __float2bfloat16_rn(v);
    float lr = v - __bfloat162float(hb);
    h = __bfloat16_as_ushort(hb);
    l = __bfloat16_as_ushort(__float2bfloat16_rn(lr));
}

__device__ __forceinline__ uint32_t awoff(int m, int k) {
    uint32_t mtile = m >> 4, kstep = k >> 4;
    uint32_t lane = ((m & 7) << 2) | ((k & 7) >> 1);
    uint32_t r = ((m >> 3) & 1) | (((k >> 3) & 1) << 1);
    return ((mtile * 16 + kstep) << 7) + (lane << 2) + r;
}
__device__ __forceinline__ uint32_t bwoff_i(int n, int k) {
    uint32_t ntile = n >> 3, kstep = k >> 4;
    uint32_t lane = ((n & 7) << 2) | ((k & 7) >> 1);
    uint32_t r = (k >> 3) & 1;
    return (((ntile * 16 + kstep) * 32 + lane) << 2) + r;
}

__device__ __forceinline__ void mma_bf16(float* c, const uint32_t* a, uint32_t b0, uint32_t b1) {
    asm volatile(
        "mma.sync.aligned.m16n8k16.row.col.f32.bf16.bf16.f32 "
        "{%0,%1,%2,%3}, {%4,%5,%6,%7}, {%8,%9}, {%0,%1,%2,%3};"
        : "+f"(c[0]), "+f"(c[1]), "+f"(c[2]), "+f"(c[3])
        : "r"(a[0]), "r"(a[1]), "r"(a[2]), "r"(a[3]), "r"(b0), "r"(b1));
}

// ---------------- k_wfrag: W[c'][c] -> B fragments (hi/lo interleaved) ----------------
__global__ void k_wfrag(const float* __restrict__ Wex, const float* __restrict__ Wq) {
    int d = blockIdx.y;
    const float* W = d ? Wq : Wex;
    int idx = blockIdx.x * 256 + threadIdx.x;   // (n, kg): n=idx>>6, kg=(idx&63)*4
    int n = idx >> 6, kg = (idx & 63) * 4;
    float4 v = *(const float4*)(W + n * C + kg);
    unsigned short h[4], l[4];
    bf16split(v.x, h[0], l[0]); bf16split(v.y, h[1], l[1]);
    bf16split(v.z, h[2], l[2]); bf16split(v.w, h[3], l[3]);
    uint32_t bb = (uint32_t)d * 65536u;
    uint32_t w0 = bwoff_i(n, kg), w1 = bwoff_i(n, kg + 2);
    g_Wf[bb + w0]     = (uint32_t)h[0] | ((uint32_t)h[1] << 16);
    g_Wf[bb + w0 + 2] = (uint32_t)l[0] | ((uint32_t)l[1] << 16);
    g_Wf[bb + w1]     = (uint32_t)h[2] | ((uint32_t)h[3] << 16);
    g_Wf[bb + w1 + 2] = (uint32_t)l[2] | ((uint32_t)l[3] << 16);
}

// ---------------- Ku ----------------
__global__ void k_u(const float* __restrict__ ex, const float* __restrict__ qf,
                    const float* __restrict__ gate) {
    __shared__ float gs[C];
    int d = blockIdx.z, b = blockIdx.y;
    gs[threadIdx.x] = gate[threadIdx.x];
    __syncthreads();
    const float* X = (d == 0 ? ex : qf) + (size_t)b * C * N;
    int j = blockIdx.x * 256 + threadIdx.x;
    float acc = 0.f;
#pragma unroll 8
    for (int c = 0; c < C; c++) acc += gs[c] * X[(size_t)c * N + j];
    g_u[d][b][j] = acc;
}

// ---------------- k_bfrag: X -> B fragments + A fragments ----------------
__global__ void __launch_bounds__(256) k_bfrag(const float* __restrict__ ex,
                                               const float* __restrict__ qf) {
    __shared__ float T[64][65];
    int z = blockIdx.z, src = z >> 1, b = z & 1;
    const float* X = (src == 0 ? ex : qf) + (size_t)b * C * N;
    int c0 = blockIdx.y * 64, n0 = blockIdx.x * 64;
    int t = threadIdx.x;
#pragma unroll
    for (int it = 0; it < 4; it++) {
        int c = (t >> 4) + it * 16;
        int n4 = (t & 15) * 4;
        float4 v = *(const float4*)(X + (size_t)(c0 + c) * N + n0 + n4);
        T[c][n4 + 0] = v.x; T[c][n4 + 1] = v.y; T[c][n4 + 2] = v.z; T[c][n4 + 3] = v.w;
    }
    __syncthreads();
    uint32_t bb = (uint32_t)(src * BATCH + b) * 1048576u;
    uint32_t ab = (uint32_t)(src * BATCH + b) * 524288u;
#pragma unroll
    for (int it = 0; it < 4; it++) {
        int nl = (t >> 4) + it * 16;
        int c4 = (t & 15) * 4;
        int n = n0 + nl;
        unsigned short h[4], l[4];
#pragma unroll
        for (int k = 0; k < 4; k++) bf16split(T[c4 + k][nl], h[k], l[k]);
        int cg = c0 + c4;
        uint32_t p0 = (uint32_t)h[0] | ((uint32_t)h[1] << 16);
        uint32_t p1 = (uint32_t)h[2] | ((uint32_t)h[3] << 16);
        uint32_t q0 = (uint32_t)l[0] | ((uint32_t)l[1] << 16);
        uint32_t q1 = (uint32_t)l[2] | ((uint32_t)l[3] << 16);
        uint32_t w0 = bwoff_i(n, cg), w1 = bwoff_i(n, cg + 2);
        g_Bf[bb + w0]     = p0;
        g_Bf[bb + w0 + 2] = q0;
        g_Bf[bb + w1]     = p1;
        g_Bf[bb + w1 + 2] = q1;
        uint32_t a0 = awoff(n, cg), a1 = awoff(n, cg + 2);
        g_XAh[ab + a0] = p0; g_XAh[ab + a1] = p1;
        g_XAl[ab + a0] = q0; g_XAl[ab + a1] = q1;
    }
}

// ---------------- K1: mproj2 — HMMA GEMM Mt[pos][c'] -> A fragments ----------------
#define OFF_AFH 0
#define OFF_AFL 65536
#define OFF_BS  131072
#define SMEM_TOT 196608

__global__ void __launch_bounds__(256, 1) k_mproj2() {
    extern __shared__ char smc[];
    uint32_t* Afh = (uint32_t*)(smc + OFF_AFH);
    uint32_t* Afl = (uint32_t*)(smc + OFF_AFL);
    uint4*    Bs4 = (uint4*)(smc + OFF_BS);       // [2][2048] uint4

    int tid = threadIdx.x, w = tid >> 5, lane = tid & 31;
    int rg = w & 3, set = w >> 2;
    int panel = blockIdx.x;                        // pos / 128
    int chalf = blockIdx.y;                        // c' half (0/1)
    int d = blockIdx.z >> 1, b = blockIdx.z & 1;
    int src = d;                                   // M[d] = W[d] @ X_src, src: 0=ex,1=qf

    const uint32_t* Agh = g_XAh + (size_t)(src * BATCH + b) * 524288 + (size_t)panel * 16384;
    const uint32_t* Agl = g_XAl + (size_t)(src * BATCH + b) * 524288 + (size_t)panel * 16384;
    const uint4* Bg = (const uint4*)g_Wf + (size_t)d * 16384;

#pragma unroll
    for (int i = 0; i < 16; i++) {
        int j = tid + i * 256;
        ((uint4*)Afh)[j] = __ldg((const uint4*)Agh + j);
        ((uint4*)Afl)[j] = __ldg((const uint4*)Agl + j);
    }

    uint4 pf[8];
#pragma unroll
    for (int i = 0; i < 8; i++) {
        int j = tid + i * 256;
        int ln = j & 31, ks = (j >> 5) & 3, ntl = j >> 7;
        pf[i] = __ldg(Bg + ((size_t)(chalf * 16 + ntl) * 16 + 0 * 4 + ks) * 32 + ln);
    }
#pragma unroll
    for (int i = 0; i < 8; i++) Bs4[tid + i * 256] = pf[i];
    __syncthreads();

    float acc[2][8][4];
#pragma unroll
    for (int mt = 0; mt < 2; mt++)
#pragma unroll
        for (int nt = 0; nt < 8; nt++)
#pragma unroll
            for (int r = 0; r < 4; r++) acc[mt][nt][r] = 0.f;

    int buf = 0;
    for (int kc = 0; kc < 4; kc++) {
        bool more = (kc + 1) < 4;
        if (more) {
#pragma unroll
            for (int i = 0; i < 8; i++) {
                int j = tid + i * 256;
                int ln = j & 31, ks = (j >> 5) & 3, ntl = j >> 7;
                pf[i] = __ldg(Bg + ((size_t)(chalf * 16 + ntl) * 16 + (kc + 1) * 4 + ks) * 32 + ln);
            }
        }
#pragma unroll
        for (int ks = 0; ks < 4; ks++) {
            int kstep = kc * 4 + ks;
            uint32_t ah0[4], al0[4], ah1[4], al1[4];
            *(uint4*)ah0 = *(const uint4*)(Afh + (((rg * 2 + 0) * 16 + kstep) << 7) + (lane << 2));
            *(uint4*)al0 = *(const uint4*)(Afl + (((rg * 2 + 0) * 16 + kstep) << 7) + (lane << 2));
            *(uint4*)ah1 = *(const uint4*)(Afh + (((rg * 2 + 1) * 16 + kstep) << 7) + (lane << 2));
            *(uint4*)al1 = *(const uint4*)(Afl + (((rg * 2 + 1) * 16 + kstep) << 7) + (lane << 2));
#pragma unroll
            for (int j = 0; j < 8; j++) {
                uint4 bf = Bs4[buf * 2048 + (((set * 8 + j) * 4 + ks) << 5) + lane];
                mma_bf16(acc[0][j], ah0, bf.x, bf.y);
                mma_bf16(acc[0][j], ah0, bf.z, bf.w);
                mma_bf16(acc[0][j], al0, bf.x, bf.y);
                mma_bf16(acc[1][j], ah1, bf.x, bf.y);
                mma_bf16(acc[1][j], ah1, bf.z, bf.w);
                mma_bf16(acc[1][j], al1, bf.x, bf.y);
            }
        }
        if (more) {
#pragma unroll
            for (int i = 0; i < 8; i++) Bs4[(buf ^ 1) * 2048 + tid + i * 256] = pf[i];
        }
        __syncthreads();
        buf ^= 1;
    }

    // epilogue: acc rows = pos, cols = c'. Write attn A-fragments (pairs along c').
    uint32_t ab = (uint32_t)(d * BATCH + b) * 524288u;
#pragma unroll
    for (int mt = 0; mt < 2; mt++) {
        uint32_t mtile = panel * 8 + rg * 2 + mt;
#pragma unroll
        for (int nt = 0; nt < 8; nt++) {
            int kcol = chalf * 128 + set * 64 + nt * 8 + ((lane & 3) << 1);
            uint32_t kstep = kcol >> 4;
            uint32_t word = ((mtile * 16 + kstep) << 7) + (lane << 2) + (nt & 1) * 2;
            unsigned short h0, l0, h1, l1, h2, l2, h3, l3;
            bf16split(acc[mt][nt][0], h0, l0);
            bf16split(acc[mt][nt][1], h1, l1);
            bf16split(acc[mt][nt][2], h2, l2);
            bf16split(acc[mt][nt][3], h3, l3);
            uint2 vh = make_uint2((uint32_t)h0 | ((uint32_t)h1 << 16),
                                  (uint32_t)h2 | ((uint32_t)h3 << 16));
            uint2 vl = make_uint2((uint32_t)l0 | ((uint32_t)l1 << 16),
                                  (uint32_t)l2 | ((uint32_t)l3 << 16));
            *(uint2*)(g_Afh + ab + word) = vh;
            *(uint2*)(g_Afl + ab + word) = vl;
        }
    }
}

// ---------------- K2: HMMA logits GEMM + online softmax ----------------
__global__ void __launch_bounds__(256, 1) k_attn_mma(float* __restrict__ out) {
    extern __shared__ char smc[];
    uint32_t* Afh = (uint32_t*)(smc + OFF_AFH);
    uint32_t* Afl = (uint32_t*)(smc + OFF_AFL);
    uint4*    Bs4 = (uint4*)(smc + OFF_BS);

    int tid = threadIdx.x, w = tid >> 5, lane = tid & 31;
    int rg = w & 3, set = w >> 2;
    int panel = blockIdx.x, b = blockIdx.y, d = blockIdx.z;
    int e0 = panel * 128;
    int src = (d == 0) ? 1 : 0;

    const uint32_t* Agh = g_Afh + (size_t)(d * BATCH + b) * 524288 + (size_t)panel * 16384;
    const uint32_t* Agl = g_Afl + (size_t)(d * BATCH + b) * 524288 + (size_t)panel * 16384;
    const uint4* Bg = (const uint4*)g_Bf + (size_t)(src * BATCH + b) * 262144;
    const float* uptr = g_u[d][b];
    __half* S = g_S[d][b];

#pragma unroll
    for (int i = 0; i < 16; i++) {
        int j = tid + i * 256;
        ((uint4*)Afh)[j] = __ldg((const uint4*)Agh + j);
        ((uint4*)Afl)[j] = __ldg((const uint4*)Agl + j);
    }

    uint4 pf[8];
#pragma unroll
    for (int i = 0; i < 8; i++) {
        int j = tid + i * 256;
        int ln = j & 31, ks = (j >> 5) & 3, ntl = j >> 7;
        pf[i] = __ldg(Bg + ((size_t)(0 * 16 + ntl) * 16 + 0 * 4 + ks) * 32 + ln);
    }
#pragma unroll
    for (int i = 0; i < 8; i++) Bs4[tid + i * 256] = pf[i];
    __syncthreads();

    float m_run[4], s_run[4], t_run[4];
#pragma unroll
    for (int i = 0; i < 4; i++) { m_run[i] = -CUDART_INF_F; s_run[i] = 0.f; t_run[i] = 0.f; }

    int buf = 0;
    for (int tile = 0; tile < 32; tile++) {
        float acc[2][8][4];
#pragma unroll
        for (int mt = 0; mt < 2; mt++)
#pragma unroll
            for (int nt = 0; nt < 8; nt++)
#pragma unroll
                for (int r = 0; r < 4; r++) acc[mt][nt][r] = 0.f;

        for (int kc = 0; kc < 4; kc++) {
            int gc = tile * 4 + kc;
            bool more = (gc + 1) < 128;
            if (more) {
                int tile2 = (gc + 1) >> 2, kc2 = (gc + 1) & 3;
#pragma unroll
                for (int i = 0; i < 8; i++) {
                    int j = tid + i * 256;
                    int ln = j & 31, ks = (j >> 5) & 3, ntl = j >> 7;
                    pf[i] = __ldg(Bg + ((size_t)(tile2 * 16 + ntl) * 16 + kc2 * 4 + ks) * 32 + ln);
                }
            }
#pragma unroll
            for (int ks = 0; ks < 4; ks++) {
                int kstep = kc * 4 + ks;
                uint32_t ah0[4], al0[4], ah1[4], al1[4];
                *(uint4*)ah0 = *(const uint4*)(Afh + (((rg * 2 + 0) * 16 + kstep) << 7) + (lane << 2));
                *(uint4*)al0 = *(const uint4*)(Afl + (((rg * 2 + 0) * 16 + kstep) << 7) + (lane << 2));
                *(uint4*)ah1 = *(const uint4*)(Afh + (((rg * 2 + 1) * 16 + kstep) << 7) + (lane << 2));
                *(uint4*)al1 = *(const uint4*)(Afl + (((rg * 2 + 1) * 16 + kstep) << 7) + (lane << 2));
#pragma unroll
                for (int j = 0; j < 8; j++) {
                    uint4 bf = Bs4[buf * 2048 + (((set * 8 + j) * 4 + ks) << 5) + lane];
                    mma_bf16(acc[0][j], ah0, bf.x, bf.y);
                    mma_bf16(acc[0][j], ah0, bf.z, bf.w);
                    mma_bf16(acc[0][j], al0, bf.x, bf.y);
                    mma_bf16(acc[1][j], ah1, bf.x, bf.y);
                    mma_bf16(acc[1][j], ah1, bf.z, bf.w);
                    mma_bf16(acc[1][j], al1, bf.x, bf.y);
                }
            }
            if (more) {
#pragma unroll
                for (int i = 0; i < 8; i++) Bs4[(buf ^ 1) * 2048 + tid + i * 256] = pf[i];
            }
            __syncthreads();
            buf ^= 1;
        }

        int qb = tile * 128 + set * 64;
        int t2 = tile * 2 + set;
#pragma unroll
        for (int mt = 0; mt < 2; mt++) {
#pragma unroll
            for (int rr = 0; rr < 2; rr++) {
                int st = mt * 2 + rr;
                int lrow = rg * 32 + mt * 16 + (lane >> 2) + rr * 8;
                int row = e0 + lrow;
                float mx = -CUDART_INF_F;
#pragma unroll
                for (int nt = 0; nt < 8; nt++)
                    mx = fmaxf(mx, fmaxf(acc[mt][nt][rr * 2], acc[mt][nt][rr * 2 + 1]));
                mx = fmaxf(mx, __shfl_xor_sync(0xffffffffu, mx, 1));
                mx = fmaxf(mx, __shfl_xor_sync(0xffffffffu, mx, 2));
                float mn = fmaxf(m_run[st], mx);
                float sc = __expf(m_run[st] - mn);
                float ps = 0.f, pu = 0.f;
                __half* Srow = S + (size_t)row * N + qb + ((lane & 3) << 1);
#pragma unroll
                for (int nt = 0; nt < 8; nt++) {
                    float v0 = acc[mt][nt][rr * 2], v1 = acc[mt][nt][rr * 2 + 1];
                    float2 u2 = __ldg((const float2*)(uptr + qb + nt * 8 + ((lane & 3) << 1)));
                    float p0 = __expf(v0 - mn), p1 = __expf(v1 - mn);
                    ps += p0 + p1;
                    pu += p0 * u2.x + p1 * u2.y;
                    *(__half2*)(Srow + nt * 8) = __floats2half2_rn(p0, p1);
                }
                ps += __shfl_xor_sync(0xffffffffu, ps, 1);
                ps += __shfl_xor_sync(0xffffffffu, ps, 2);
                pu += __shfl_xor_sync(0xffffffffu, pu, 1);
                pu += __shfl_xor_sync(0xffffffffu, pu, 2);
                s_run[st] = s_run[st] * sc + ps;
                t_run[st] = t_run[st] * sc + pu;
                m_run[st] = mn;
                if ((lane & 3) == 0) g_mt[d][b][t2][row] = mn;
            }
        }
    }

    float* mrg = (float*)(smc + OFF_BS);
    if (set == 1 && (lane & 3) == 0) {
#pragma unroll
        for (int st = 0; st < 4; st++) {
            int mt = st >> 1, rr = st & 1;
            int lrow = rg * 32 + mt * 16 + (lane >> 2) + rr * 8;
            mrg[lrow * 3 + 0] = m_run[st];
            mrg[lrow * 3 + 1] = s_run[st];
            mrg[lrow * 3 + 2] = t_run[st];
        }
    }
    __syncthreads();
    if (set == 0 && (lane & 3) == 0) {
#pragma unroll
        for (int st = 0; st < 4; st++) {
            int mt = st >> 1, rr = st & 1;
            int lrow = rg * 32 + mt * 16 + (lane >> 2) + rr * 8;
            int e = e0 + lrow;
            float m1 = mrg[lrow * 3 + 0];
            float s1 = mrg[lrow * 3 + 1];
            float t1 = mrg[lrow * 3 + 2];
            float mf = fmaxf(m_run[st], m1);
            float sc0 = __expf(m_run[st] - mf);
            float sc1 = __expf(m1 - mf);
            float sf = s_run[st] * sc0 + s1 * sc1;
            float tf = t_run[st] * sc0 + t1 * sc1;
            g_rm[d][b][e] = mf;
            g_rs[d][b][e] = sf;
            float zv = tf / sf;
            out[(size_t)d * (BATCH * N) + (size_t)b * N + e] = 1.f / (1.f + __expf(-zv));
        }
    }
}

// ---------------- K3: rescale + transpose-write A ----------------
__global__ void __launch_bounds__(256) k_norm_t(float* __restrict__ out) {
    __shared__ float T[64][65];
    __shared__ float fs[64];
    int z = blockIdx.z, d = z >> 1, b = z & 1;
    const __half* S = g_S[d][b];
    const float* rm = g_rm[d][b];
    const float* rs = g_rs[d][b];
    float* Aout = out + 16384 + (size_t)d * (size_t)BATCH * N * N + (size_t)b * (size_t)N * N;
    int e0 = blockIdx.y * 64, q0 = blockIdx.x * 64;
    int t2 = blockIdx.x;
    int t = threadIdx.x;

    if (t < 64) {
        int e = e0 + t;
        fs[t] = __expf(g_mt[d][b][t2][e] - rm[e]) * __frcp_rn(rs[e]);
    }
    __syncthreads();

#pragma unroll
    for (int it = 0; it < 4; it++) {
        int e  = (t >> 4) + it * 16;
        int q4 = (t & 15) * 4;
        uint2 rd = *(const uint2*)(S + (size_t)(e0 + e) * N + q0 + q4);
        float2 f0 = __half22float2(*(__half2*)&rd.x);
        float2 f1 = __half22float2(*(__half2*)&rd.y);
        float f = fs[e];
        T[e][q4 + 0] = f0.x * f;
        T[e][q4 + 1] = f0.y * f;
        T[e][q4 + 2] = f1.x * f;
        T[e][q4 + 3] = f1.y * f;
    }
    __syncthreads();
#pragma unroll
    for (int it = 0; it < 4; it++) {
        int q  = (t >> 4) + it * 16;
        int e4 = (t & 15) * 4;
        float4 o;
        o.x = T[e4 + 0][q];
        o.y = T[e4 + 1][q];
        o.z = T[e4 + 2][q];
        o.w = T[e4 + 3][q];
        *(float4*)(Aout + (size_t)(q0 + q) * N + e0 + e4) = o;
    }
}

// ---------------- launch ----------------
extern "C" void kernel_launch(void* const* d_in, const int* in_sizes, int n_in,
                              void* d_out, int out_size) {
    const float* ex   = (const float*)d_in[0];
    const float* qf   = (const float*)d_in[1];
    const float* Wex  = (const float*)d_in[2];
    const float* Wq   = (const float*)d_in[3];
    const float* gate = (const float*)d_in[4];
    float* out = (float*)d_out;

    cudaFuncSetAttribute(k_mproj2,   cudaFuncAttributeMaxDynamicSharedMemorySize, SMEM_TOT);
    cudaFuncSetAttribute(k_attn_mma, cudaFuncAttributeMaxDynamicSharedMemorySize, SMEM_TOT);

    k_wfrag    <<<dim3(64, 2), 256>>>(Wex, Wq);
    k_u        <<<dim3(N / 256, BATCH, 2), 256>>>(ex, qf, gate);
    k_bfrag    <<<dim3(N / 64, C / 64, 4), 256>>>(ex, qf);
    k_mproj2   <<<dim3(32, 2, 4), 256, SMEM_TOT>>>();
    k_attn_mma <<<dim3(32, BATCH, 2), 256, SMEM_TOT>>>(out);
    k_norm_t   <<<dim3(N / 64, N / 64, 4), 256>>>(out);
}